// round 1
// baseline (speedup 1.0000x reference)
#include <cuda_runtime.h>
#include <math.h>

#define DIMC 768
#define HEADS 12
#define NB 8
#define NTOK 1024
#define DH 64

// Scratch: qkv as [k][b][h][d][n], ctx as [b][c][n]
__device__ float g_qkv[3ull * NB * HEADS * DH * NTOK];   // ~75.5 MB
__device__ float g_ctx[(size_t)NB * DIMC * NTOK];        // ~25 MB

// ---------------------------------------------------------------------------
// Kernel 1: qkv = tokens @ w_qkv  (tokens[b,n,c] = x[b,c,n]), scatter to g_qkv
// Grid: (2304/64, 8192/64) = (36, 128), 256 threads
// ---------------------------------------------------------------------------
__global__ void qkv_gemm(const float* __restrict__ x, const float* __restrict__ w) {
    __shared__ float As[16][64];
    __shared__ float Bs[16][64];
    __shared__ float Cs[64][65];
    int t  = threadIdx.x;
    int tx = t & 15, ty = t >> 4;
    int j0 = blockIdx.x << 6;          // output col tile (0..2304)
    int by = blockIdx.y;               // row tile over 8192 = 8 batches * 1024
    int b  = by >> 4;
    int n0 = (by & 15) << 6;
    const float* A = x + (size_t)b * DIMC * NTOK;   // [c][n]

    float acc[4][4] = {};
    int mm = (t * 4) & 63, kk = (t * 4) >> 6;

    for (int k0 = 0; k0 < DIMC; k0 += 16) {
        __syncthreads();
        *(float4*)&As[kk][mm] = *(const float4*)&A[(size_t)(k0 + kk) * NTOK + n0 + mm];
        *(float4*)&Bs[kk][mm] = *(const float4*)&w[(size_t)(k0 + kk) * (3 * DIMC) + j0 + mm];
        __syncthreads();
#pragma unroll
        for (int kq = 0; kq < 16; kq++) {
            float4 a  = *(float4*)&As[kq][ty * 4];
            float4 bb = *(float4*)&Bs[kq][tx * 4];
            float av[4] = {a.x, a.y, a.z, a.w};
            float bv[4] = {bb.x, bb.y, bb.z, bb.w};
#pragma unroll
            for (int i = 0; i < 4; i++)
#pragma unroll
                for (int j = 0; j < 4; j++)
                    acc[i][j] += av[i] * bv[j];
        }
    }
    __syncthreads();
#pragma unroll
    for (int i = 0; i < 4; i++)
#pragma unroll
        for (int j = 0; j < 4; j++)
            Cs[tx * 4 + j][ty * 4 + i] = acc[i][j];
    __syncthreads();

    // Scatter: j = d*36 + k*12 + h  ->  g_qkv[k][b][h][d][n], coalesced along n
#pragma unroll
    for (int r = 0; r < 16; r++) {
        int e  = r * 256 + t;
        int m  = e & 63;
        int jl = e >> 6;
        int j  = j0 + jl;
        int h  = j % 12;
        int kq = (j / 12) % 3;
        int d  = j / 36;
        g_qkv[((((size_t)kq * NB + b) * HEADS + h) * DH + d) * NTOK + n0 + m] = Cs[jl][m];
    }
}

// ---------------------------------------------------------------------------
// Kernel 2: flash-style attention. Q,K,V in [d][n] per head; writes ctx[b][c][n].
// Grid: (16 qtiles, 96 heads), 256 threads, 66.5 KB dynamic smem.
// ---------------------------------------------------------------------------
__global__ void attn_kernel() {
    extern __shared__ float sm[];
    float* Qs = sm;                 // [64 d][64 i]     stride 64
    float* Ks = Qs + 4096;          // [64 d][64 j]     stride 64
    float* Vs = Ks + 4096;          // [64 j][64 d]     stride 68 (pad)
    float* Ps = Vs + 64 * 68;       // [64 i][64 j]     stride 64

    int t  = threadIdx.x;
    int tx = t & 15, ty = t >> 4;
    int bh = blockIdx.y;            // b*12 + h
    int n0 = blockIdx.x * 64;

    size_t head_off = (size_t)bh * DH * NTOK;
    const float* Q = g_qkv + head_off;
    const float* K = g_qkv + (size_t)(NB * HEADS + bh) * DH * NTOK;
    const float* V = g_qkv + (size_t)(2 * NB * HEADS + bh) * DH * NTOK;

    // Load Q tile, pre-scaled by sqrt(d_head)=8
#pragma unroll
    for (int rr = 0; rr < 4; rr++) {
        int e = (rr * 256 + t) * 4;
        int i = e & 63, d = e >> 6;
        float4 q4 = *(const float4*)&Q[(size_t)d * NTOK + n0 + i];
        q4.x *= 8.f; q4.y *= 8.f; q4.z *= 8.f; q4.w *= 8.f;
        *(float4*)&Qs[d * 64 + i] = q4;
    }

    float m_run[4], l_run[4], o[4][4];
#pragma unroll
    for (int i = 0; i < 4; i++) {
        m_run[i] = -1e30f; l_run[i] = 0.f;
#pragma unroll
        for (int j = 0; j < 4; j++) o[i][j] = 0.f;
    }

    for (int kt = 0; kt < 16; kt++) {
        int jn0 = kt * 64;
        __syncthreads();
        // Fill K [d][j] (coalesced) and V transposed to [j][d]
#pragma unroll
        for (int rr = 0; rr < 4; rr++) {
            int e = (rr * 256 + t) * 4;
            int j = e & 63, d = e >> 6;
            *(float4*)&Ks[d * 64 + j] = *(const float4*)&K[(size_t)d * NTOK + jn0 + j];
            float4 v4 = *(const float4*)&V[(size_t)d * NTOK + jn0 + j];
            Vs[(j + 0) * 68 + d] = v4.x;
            Vs[(j + 1) * 68 + d] = v4.y;
            Vs[(j + 2) * 68 + d] = v4.z;
            Vs[(j + 3) * 68 + d] = v4.w;
        }
        __syncthreads();

        // S = Q^T K  (4x4 per thread)
        float s[4][4] = {};
#pragma unroll
        for (int d = 0; d < 64; d++) {
            float4 a  = *(float4*)&Qs[d * 64 + ty * 4];
            float4 kb = *(float4*)&Ks[d * 64 + tx * 4];
            float av[4] = {a.x, a.y, a.z, a.w};
            float bv[4] = {kb.x, kb.y, kb.z, kb.w};
#pragma unroll
            for (int ii = 0; ii < 4; ii++)
#pragma unroll
                for (int jj = 0; jj < 4; jj++)
                    s[ii][jj] += av[ii] * bv[jj];
        }

        // Online softmax update (row group = 16 tx lanes, consistent via shfl)
#pragma unroll
        for (int ii = 0; ii < 4; ii++) {
            float rm = fmaxf(fmaxf(s[ii][0], s[ii][1]), fmaxf(s[ii][2], s[ii][3]));
#pragma unroll
            for (int off = 8; off; off >>= 1)
                rm = fmaxf(rm, __shfl_xor_sync(0xffffffffu, rm, off));
            float m_new = fmaxf(m_run[ii], rm);
            float alpha = __expf(m_run[ii] - m_new);
            float rs = 0.f;
#pragma unroll
            for (int jj = 0; jj < 4; jj++) {
                float p = __expf(s[ii][jj] - m_new);
                s[ii][jj] = p;
                rs += p;
            }
#pragma unroll
            for (int off = 8; off; off >>= 1)
                rs += __shfl_xor_sync(0xffffffffu, rs, off);
            l_run[ii] = l_run[ii] * alpha + rs;
            m_run[ii] = m_new;
#pragma unroll
            for (int dd = 0; dd < 4; dd++) o[ii][dd] *= alpha;
#pragma unroll
            for (int jj = 0; jj < 4; jj++)
                Ps[(ty * 4 + ii) * 64 + tx * 4 + jj] = s[ii][jj];
        }
        __syncthreads();

        // O += P @ V   (vectorized over j via float4 P rows, V rows [j][d])
#pragma unroll
        for (int jv = 0; jv < 16; jv++) {
            float4 pv[4];
#pragma unroll
            for (int ii = 0; ii < 4; ii++)
                pv[ii] = *(float4*)&Ps[(ty * 4 + ii) * 64 + jv * 4];
            const float* pf = (const float*)pv;
#pragma unroll
            for (int r = 0; r < 4; r++) {
                int j = jv * 4 + r;
                float4 vv = *(float4*)&Vs[j * 68 + tx * 4];
                float vvv[4] = {vv.x, vv.y, vv.z, vv.w};
#pragma unroll
                for (int ii = 0; ii < 4; ii++) {
                    float pva = pf[ii * 4 + r];
#pragma unroll
                    for (int dd = 0; dd < 4; dd++)
                        o[ii][dd] += pva * vvv[dd];
                }
            }
        }
    }

    // Normalize, stage O^T [d][i] into Ps, coalesced store into ctx[b][c][n]
    __syncthreads();
#pragma unroll
    for (int ii = 0; ii < 4; ii++) {
        float inv = 1.f / l_run[ii];
#pragma unroll
        for (int dd = 0; dd < 4; dd++)
            Ps[(tx * 4 + dd) * 64 + ty * 4 + ii] = o[ii][dd] * inv;
    }
    __syncthreads();

    int b = bh / HEADS, h = bh % HEADS;
    float* ctxp = g_ctx + ((size_t)b * DIMC + h * DH) * NTOK;
#pragma unroll
    for (int rr = 0; rr < 16; rr++) {
        int e = rr * 256 + t;
        int i = e & 63, d = e >> 6;
        ctxp[(size_t)d * NTOK + n0 + i] = Ps[d * 64 + i];
    }
}

// ---------------------------------------------------------------------------
// Kernel 3: out[b][c'][n] = sum_c ctx[b][c][n] * w_proj[c][c']
// Grid: (768/64, 8192/64) = (12, 128), 256 threads
// ---------------------------------------------------------------------------
__global__ void proj_gemm(const float* __restrict__ w, float* __restrict__ out) {
    __shared__ float As[16][64];
    __shared__ float Bs[16][64];
    __shared__ float Cs[64][65];
    int t  = threadIdx.x;
    int tx = t & 15, ty = t >> 4;
    int j0 = blockIdx.x << 6;
    int by = blockIdx.y;
    int b  = by >> 4;
    int n0 = (by & 15) << 6;
    const float* A = g_ctx + (size_t)b * DIMC * NTOK;   // [c][n]

    float acc[4][4] = {};
    int mm = (t * 4) & 63, kk = (t * 4) >> 6;

    for (int k0 = 0; k0 < DIMC; k0 += 16) {
        __syncthreads();
        *(float4*)&As[kk][mm] = *(const float4*)&A[(size_t)(k0 + kk) * NTOK + n0 + mm];
        *(float4*)&Bs[kk][mm] = *(const float4*)&w[(size_t)(k0 + kk) * DIMC + j0 + mm];
        __syncthreads();
#pragma unroll
        for (int kq = 0; kq < 16; kq++) {
            float4 a  = *(float4*)&As[kq][ty * 4];
            float4 bb = *(float4*)&Bs[kq][tx * 4];
            float av[4] = {a.x, a.y, a.z, a.w};
            float bv[4] = {bb.x, bb.y, bb.z, bb.w};
#pragma unroll
            for (int i = 0; i < 4; i++)
#pragma unroll
                for (int j = 0; j < 4; j++)
                    acc[i][j] += av[i] * bv[j];
        }
    }
    __syncthreads();
#pragma unroll
    for (int i = 0; i < 4; i++)
#pragma unroll
        for (int j = 0; j < 4; j++)
            Cs[tx * 4 + j][ty * 4 + i] = acc[i][j];
    __syncthreads();

#pragma unroll
    for (int r = 0; r < 16; r++) {
        int e  = r * 256 + t;
        int m  = e & 63;
        int jl = e >> 6;
        out[((size_t)b * DIMC + j0 + jl) * NTOK + n0 + m] = Cs[jl][m];
    }
}

// ---------------------------------------------------------------------------
extern "C" void kernel_launch(void* const* d_in, const int* in_sizes, int n_in,
                              void* d_out, int out_size) {
    const float* x      = (const float*)d_in[0];
    const float* w_qkv  = (const float*)d_in[1];
    const float* w_proj = (const float*)d_in[2];
    float* out = (float*)d_out;

    const int attn_smem = (4096 + 4096 + 64 * 68 + 4096) * 4;   // 66560 B
    cudaFuncSetAttribute(attn_kernel, cudaFuncAttributeMaxDynamicSharedMemorySize, attn_smem);

    qkv_gemm<<<dim3(36, 128), 256>>>(x, w_qkv);
    attn_kernel<<<dim3(16, 96), 256, attn_smem>>>();
    proj_gemm<<<dim3(12, 128), 256>>>(w_proj, out);
}

// round 3
// speedup vs baseline: 2.4563x; 2.4563x over previous
#include <cuda_runtime.h>
#include <cuda_bf16.h>
#include <cstdint>
#include <math.h>

#define DIMC 768
#define HEADS 12
#define NB 8
#define NTOK 1024
#define DH 64

// ---------------------------------------------------------------------------
// Global scratch
// ---------------------------------------------------------------------------
__device__ float g_qkv[3ull * NB * HEADS * DH * NTOK];            // [k][b][h][d][n] fp32
__device__ __nv_bfloat16 g_Xh[(size_t)NB * NTOK * DIMC];          // tokens [m][k]
__device__ __nv_bfloat16 g_Xl[(size_t)NB * NTOK * DIMC];
__device__ __nv_bfloat16 g_Wqh[(size_t)3 * DIMC * DIMC];          // w_qkv^T [j][k]
__device__ __nv_bfloat16 g_Wql[(size_t)3 * DIMC * DIMC];
__device__ __nv_bfloat16 g_Wph[(size_t)DIMC * DIMC];              // w_proj^T [j][k]
__device__ __nv_bfloat16 g_Wpl[(size_t)DIMC * DIMC];
__device__ __nv_bfloat16 g_Ch[(size_t)NB * NTOK * DIMC];          // ctx [m][k]
__device__ __nv_bfloat16 g_Cl[(size_t)NB * NTOK * DIMC];

// ---------------------------------------------------------------------------
// Helpers (portable PTX only: ldmatrix + mma.sync, sm_80+)
// ---------------------------------------------------------------------------
__device__ __forceinline__ uint32_t smem_to_u32(const void* p) {
    uint32_t a;
    asm("{ .reg .u64 t; cvta.to.shared.u64 t, %1; cvt.u32.u64 %0, t; }" : "=r"(a) : "l"(p));
    return a;
}
__device__ __forceinline__ void ldsm_x4(uint32_t* r, uint32_t a) {
    asm volatile("ldmatrix.sync.aligned.m8n8.x4.shared.b16 {%0,%1,%2,%3}, [%4];"
        : "=r"(r[0]), "=r"(r[1]), "=r"(r[2]), "=r"(r[3]) : "r"(a));
}
__device__ __forceinline__ void mma_bf16(float* d, const uint32_t* a, const uint32_t* b) {
    asm volatile("mma.sync.aligned.m16n8k16.row.col.f32.bf16.bf16.f32 "
        "{%0,%1,%2,%3}, {%4,%5,%6,%7}, {%8,%9}, {%0,%1,%2,%3};"
        : "+f"(d[0]), "+f"(d[1]), "+f"(d[2]), "+f"(d[3])
        : "r"(a[0]), "r"(a[1]), "r"(a[2]), "r"(a[3]), "r"(b[0]), "r"(b[1]));
}

// ---------------------------------------------------------------------------
// Split + transpose: src[R][C] fp32 -> dh/dl[C][R] bf16 (hi/lo), batched over z
// ---------------------------------------------------------------------------
__device__ __forceinline__ void split_transpose_body(const float* __restrict__ src,
    __nv_bfloat16* __restrict__ dh, __nv_bfloat16* __restrict__ dl, int R, int C)
{
    __shared__ float tile[32][33];
    size_t bo = (size_t)blockIdx.z * R * C;
    int c0 = blockIdx.x << 5, r0 = blockIdx.y << 5;
    int tx = threadIdx.x & 31, ty = threadIdx.x >> 5;
#pragma unroll
    for (int i = 0; i < 32; i += 8)
        tile[ty + i][tx] = src[bo + (size_t)(r0 + ty + i) * C + c0 + tx];
    __syncthreads();
#pragma unroll
    for (int i = 0; i < 32; i += 8) {
        float v = tile[tx][ty + i];
        __nv_bfloat16 hv = __float2bfloat16(v);
        float lo = v - __bfloat162float(hv);
        size_t o = bo + (size_t)(c0 + ty + i) * R + (r0 + tx);
        dh[o] = hv;
        dl[o] = __float2bfloat16(lo);
    }
}
__global__ void split_x_kernel(const float* __restrict__ x)  { split_transpose_body(x, g_Xh, g_Xl, DIMC, NTOK); }
__global__ void split_wq_kernel(const float* __restrict__ w) { split_transpose_body(w, g_Wqh, g_Wql, DIMC, 3 * DIMC); }
__global__ void split_wp_kernel(const float* __restrict__ w) { split_transpose_body(w, g_Wph, g_Wpl, DIMC, DIMC); }

// ---------------------------------------------------------------------------
// bf16x3 mma.sync GEMM: C[128m x 128n] = A[m][k] * B[n][k]^T, K=768
// 256 threads = 8 warps (2m x 4n), warp tile 64x32, smem K-chunks of 64.
// ---------------------------------------------------------------------------
#define SA_STRIDE 72            // bf16 elements per smem row (64 + 8 pad)
#define TILE_BYTES (128 * SA_STRIDE * 2)

__device__ __forceinline__ void load_tile(const __nv_bfloat16* __restrict__ g,
    size_t row0, __nv_bfloat16* s, int kc, int t)
{
#pragma unroll
    for (int p = 0; p < 4; p++) {
        int lin = p * 256 + t;
        int row = lin >> 3, seg = lin & 7;
        uint4 v = *(const uint4*)(g + (row0 + row) * (size_t)DIMC + kc + seg * 8);
        *(uint4*)(s + row * SA_STRIDE + seg * 8) = v;
    }
}

__device__ __forceinline__ void gemm_mma(const __nv_bfloat16* __restrict__ Ah,
    const __nv_bfloat16* __restrict__ Al, const __nv_bfloat16* __restrict__ Bh,
    const __nv_bfloat16* __restrict__ Bl, float* __restrict__ outp, int mode)
{
    extern __shared__ char smem[];
    const uint32_t sb = smem_to_u32(smem);
    __nv_bfloat16* sAh = (__nv_bfloat16*)smem;
    __nv_bfloat16* sAl = sAh + 128 * SA_STRIDE;
    __nv_bfloat16* sBh = sAl + 128 * SA_STRIDE;
    __nv_bfloat16* sBl = sBh + 128 * SA_STRIDE;
    const uint32_t offAh = 0, offAl = TILE_BYTES, offBh = 2 * TILE_BYTES, offBl = 3 * TILE_BYTES;

    int t = threadIdx.x, lane = t & 31, wid = t >> 5;
    int wm = (wid & 1) * 64, wn = (wid >> 1) * 32;

    size_t m0 = (size_t)blockIdx.x * 128;
    int j0 = blockIdx.y * 128;

    float acc[4][4][4] = {};

    int arow = lane & 15;
    int acolp = (lane >> 4) << 3;
    int brow = (lane & 7) + ((lane >> 4) & 1) * 8;
    int bcolp = ((lane >> 3) & 1) * 8;

    for (int c = 0; c < 12; c++) {
        __syncthreads();
        int kc = c * 64;
        load_tile(Ah, m0, sAh, kc, t);
        load_tile(Al, m0, sAl, kc, t);
        load_tile(Bh, (size_t)j0, sBh, kc, t);
        load_tile(Bl, (size_t)j0, sBl, kc, t);
        __syncthreads();
#pragma unroll
        for (int ks = 0; ks < 4; ks++) {
            uint32_t ah[4][4], al[4][4], bh[2][4], bl[2][4];
            int acol = ks * 16 + acolp;
            int bcol = ks * 16 + bcolp;
#pragma unroll
            for (int mt = 0; mt < 4; mt++) {
                uint32_t ad = sb + offAh + ((wm + mt * 16 + arow) * SA_STRIDE + acol) * 2;
                ldsm_x4(ah[mt], ad);
                ldsm_x4(al[mt], ad + (offAl - offAh));
            }
#pragma unroll
            for (int ntp = 0; ntp < 2; ntp++) {
                uint32_t bd = sb + offBh + ((wn + ntp * 16 + brow) * SA_STRIDE + bcol) * 2;
                ldsm_x4(bh[ntp], bd);
                ldsm_x4(bl[ntp], bd + (offBl - offBh));
            }
#pragma unroll
            for (int mt = 0; mt < 4; mt++)
#pragma unroll
                for (int nt = 0; nt < 4; nt++) {
                    const uint32_t* bph = &bh[nt >> 1][(nt & 1) * 2];
                    const uint32_t* bpl = &bl[nt >> 1][(nt & 1) * 2];
                    mma_bf16(acc[mt][nt], ah[mt], bph);
                    mma_bf16(acc[mt][nt], al[mt], bph);
                    mma_bf16(acc[mt][nt], ah[mt], bpl);
                }
        }
    }

    // Stage C through smem for coalesced stores. Cs[128 j][132 m] fp32.
    __syncthreads();
    float* Cs = (float*)smem;
    int g = lane >> 2, tq = lane & 3;
#pragma unroll
    for (int mt = 0; mt < 4; mt++)
#pragma unroll
        for (int nt = 0; nt < 4; nt++) {
            int ml = wm + mt * 16 + g;
            int jl = wn + nt * 8 + tq * 2;
            Cs[jl * 132 + ml]           = acc[mt][nt][0];
            Cs[(jl + 1) * 132 + ml]     = acc[mt][nt][1];
            Cs[jl * 132 + ml + 8]       = acc[mt][nt][2];
            Cs[(jl + 1) * 132 + ml + 8] = acc[mt][nt][3];
        }
    __syncthreads();

    int bq = (int)(m0 >> 10);
    int n0 = (int)(m0 & 1023);
#pragma unroll
    for (int r = 0; r < 16; r++) {
        int e = r * 256 + t;
        int jl = e >> 5, seg = e & 31;
        float4 v = *(float4*)&Cs[jl * 132 + seg * 4];
        int j = j0 + jl;
        if (mode == 0) {
            int h = j % 12, kq = (j / 12) % 3, d = j / 36;
            *(float4*)&outp[((((size_t)kq * NB + bq) * HEADS + h) * DH + d) * NTOK + n0 + seg * 4] = v;
        } else {
            *(float4*)&outp[((size_t)bq * DIMC + j) * NTOK + n0 + seg * 4] = v;
        }
    }
}

__global__ void __launch_bounds__(256, 1) qkv_mma() {
    gemm_mma(g_Xh, g_Xl, g_Wqh, g_Wql, g_qkv, 0);
}
__global__ void __launch_bounds__(256, 1) proj_mma(float* __restrict__ out) {
    gemm_mma(g_Ch, g_Cl, g_Wph, g_Wpl, out, 1);
}

// ---------------------------------------------------------------------------
// Flash attention (fp32 SIMT); epilogue writes ctx bf16 hi/lo [b][n][c]
// ---------------------------------------------------------------------------
__global__ void attn_kernel() {
    extern __shared__ float sm[];
    float* Qs = sm;                 // [64 d][64 i]
    float* Ks = Qs + 4096;          // [64 d][64 j]
    float* Vs = Ks + 4096;          // [64 j][64 d] pad 68
    float* Ps = Vs + 64 * 68;       // [64 i][64 j]

    int t  = threadIdx.x;
    int tx = t & 15, ty = t >> 4;
    int bh = blockIdx.y;
    int n0 = blockIdx.x * 64;

    const float* Q = g_qkv + (size_t)bh * DH * NTOK;
    const float* K = g_qkv + (size_t)(NB * HEADS + bh) * DH * NTOK;
    const float* V = g_qkv + (size_t)(2 * NB * HEADS + bh) * DH * NTOK;

#pragma unroll
    for (int rr = 0; rr < 4; rr++) {
        int e = (rr * 256 + t) * 4;
        int i = e & 63, d = e >> 6;
        float4 q4 = *(const float4*)&Q[(size_t)d * NTOK + n0 + i];
        q4.x *= 8.f; q4.y *= 8.f; q4.z *= 8.f; q4.w *= 8.f;
        *(float4*)&Qs[d * 64 + i] = q4;
    }

    float m_run[4], l_run[4], o[4][4];
#pragma unroll
    for (int i = 0; i < 4; i++) {
        m_run[i] = -1e30f; l_run[i] = 0.f;
#pragma unroll
        for (int j = 0; j < 4; j++) o[i][j] = 0.f;
    }

    for (int kt = 0; kt < 16; kt++) {
        int jn0 = kt * 64;
        __syncthreads();
#pragma unroll
        for (int rr = 0; rr < 4; rr++) {
            int e = (rr * 256 + t) * 4;
            int j = e & 63, d = e >> 6;
            *(float4*)&Ks[d * 64 + j] = *(const float4*)&K[(size_t)d * NTOK + jn0 + j];
            float4 v4 = *(const float4*)&V[(size_t)d * NTOK + jn0 + j];
            Vs[(j + 0) * 68 + d] = v4.x;
            Vs[(j + 1) * 68 + d] = v4.y;
            Vs[(j + 2) * 68 + d] = v4.z;
            Vs[(j + 3) * 68 + d] = v4.w;
        }
        __syncthreads();

        float s[4][4] = {};
#pragma unroll
        for (int d = 0; d < 64; d++) {
            float4 a  = *(float4*)&Qs[d * 64 + ty * 4];
            float4 kb = *(float4*)&Ks[d * 64 + tx * 4];
            float av[4] = {a.x, a.y, a.z, a.w};
            float bv[4] = {kb.x, kb.y, kb.z, kb.w};
#pragma unroll
            for (int ii = 0; ii < 4; ii++)
#pragma unroll
                for (int jj = 0; jj < 4; jj++)
                    s[ii][jj] += av[ii] * bv[jj];
        }

#pragma unroll
        for (int ii = 0; ii < 4; ii++) {
            float rm = fmaxf(fmaxf(s[ii][0], s[ii][1]), fmaxf(s[ii][2], s[ii][3]));
#pragma unroll
            for (int off = 8; off; off >>= 1)
                rm = fmaxf(rm, __shfl_xor_sync(0xffffffffu, rm, off));
            float m_new = fmaxf(m_run[ii], rm);
            float alpha = __expf(m_run[ii] - m_new);
            float rs = 0.f;
#pragma unroll
            for (int jj = 0; jj < 4; jj++) {
                float p = __expf(s[ii][jj] - m_new);
                s[ii][jj] = p;
                rs += p;
            }
#pragma unroll
            for (int off = 8; off; off >>= 1)
                rs += __shfl_xor_sync(0xffffffffu, rs, off);
            l_run[ii] = l_run[ii] * alpha + rs;
            m_run[ii] = m_new;
#pragma unroll
            for (int dd = 0; dd < 4; dd++) o[ii][dd] *= alpha;
#pragma unroll
            for (int jj = 0; jj < 4; jj++)
                Ps[(ty * 4 + ii) * 64 + tx * 4 + jj] = s[ii][jj];
        }
        __syncthreads();

#pragma unroll
        for (int jv = 0; jv < 16; jv++) {
            float4 pv[4];
#pragma unroll
            for (int ii = 0; ii < 4; ii++)
                pv[ii] = *(float4*)&Ps[(ty * 4 + ii) * 64 + jv * 4];
            const float* pf = (const float*)pv;
#pragma unroll
            for (int r = 0; r < 4; r++) {
                int j = jv * 4 + r;
                float4 vv = *(float4*)&Vs[j * 68 + tx * 4];
                float vvv[4] = {vv.x, vv.y, vv.z, vv.w};
#pragma unroll
                for (int ii = 0; ii < 4; ii++) {
                    float pva = pf[ii * 4 + r];
#pragma unroll
                    for (int dd = 0; dd < 4; dd++)
                        o[ii][dd] += pva * vvv[dd];
                }
            }
        }
    }

    // Epilogue: ctx[b][n][c] bf16 hi/lo (c = h*64 + tx*4 + dd contiguous)
    int b = bh / HEADS, h = bh % HEADS;
#pragma unroll
    for (int ii = 0; ii < 4; ii++) {
        float inv = 1.f / l_run[ii];
        int n = n0 + ty * 4 + ii;
        size_t off = ((size_t)b * NTOK + n) * DIMC + h * DH + tx * 4;
#pragma unroll
        for (int dd = 0; dd < 4; dd += 2) {
            float v0 = o[ii][dd] * inv, v1 = o[ii][dd + 1] * inv;
            __nv_bfloat16 h0 = __float2bfloat16(v0), h1 = __float2bfloat16(v1);
            __nv_bfloat16 l0 = __float2bfloat16(v0 - __bfloat162float(h0));
            __nv_bfloat16 l1 = __float2bfloat16(v1 - __bfloat162float(h1));
            __nv_bfloat162 hp; hp.x = h0; hp.y = h1;
            __nv_bfloat162 lp; lp.x = l0; lp.y = l1;
            *(__nv_bfloat162*)(g_Ch + off + dd) = hp;
            *(__nv_bfloat162*)(g_Cl + off + dd) = lp;
        }
    }
}

// ---------------------------------------------------------------------------
extern "C" void kernel_launch(void* const* d_in, const int* in_sizes, int n_in,
                              void* d_out, int out_size) {
    const float* x      = (const float*)d_in[0];
    const float* w_qkv  = (const float*)d_in[1];
    const float* w_proj = (const float*)d_in[2];
    float* out = (float*)d_out;

    const int attn_smem = (4096 + 4096 + 64 * 68 + 4096) * 4;   // 66560 B
    const int gemm_smem = 4 * TILE_BYTES;                        // 73728 B
    cudaFuncSetAttribute(attn_kernel, cudaFuncAttributeMaxDynamicSharedMemorySize, attn_smem);
    cudaFuncSetAttribute(qkv_mma,     cudaFuncAttributeMaxDynamicSharedMemorySize, gemm_smem);
    cudaFuncSetAttribute(proj_mma,    cudaFuncAttributeMaxDynamicSharedMemorySize, gemm_smem);

    split_x_kernel <<<dim3(NTOK / 32, DIMC / 32, NB), 256>>>(x);
    split_wq_kernel<<<dim3(3 * DIMC / 32, DIMC / 32, 1), 256>>>(w_qkv);
    split_wp_kernel<<<dim3(DIMC / 32, DIMC / 32, 1), 256>>>(w_proj);
    qkv_mma <<<dim3(64, 18), 256, gemm_smem>>>();
    attn_kernel<<<dim3(16, 96), 256, attn_smem>>>();
    proj_mma<<<dim3(64, 6), 256, gemm_smem>>>(out);
}

// round 4
// speedup vs baseline: 4.2384x; 1.7255x over previous
#include <cuda_runtime.h>
#include <cuda_bf16.h>
#include <cstdint>
#include <math.h>

#define DIMC 768
#define HEADS 12
#define NB 8
#define NTOK 1024
#define DH 64
#define NBH (NB * HEADS)

// ---------------------------------------------------------------------------
// Global scratch
// ---------------------------------------------------------------------------
__device__ float g_qkv[3ull * NBH * DH * NTOK];                   // [k][bh][d][n] fp32
__device__ __nv_bfloat16 g_Xh[(size_t)NB * NTOK * DIMC];          // tokens [m][k]
__device__ __nv_bfloat16 g_Xl[(size_t)NB * NTOK * DIMC];
__device__ __nv_bfloat16 g_Wqh[(size_t)3 * DIMC * DIMC];          // w_qkv^T [j][k]
__device__ __nv_bfloat16 g_Wql[(size_t)3 * DIMC * DIMC];
__device__ __nv_bfloat16 g_Wph[(size_t)DIMC * DIMC];              // w_proj^T [j][k]
__device__ __nv_bfloat16 g_Wpl[(size_t)DIMC * DIMC];
__device__ __nv_bfloat16 g_Ch[(size_t)NB * NTOK * DIMC];          // ctx [m][k]
__device__ __nv_bfloat16 g_Cl[(size_t)NB * NTOK * DIMC];
// Attention operands (bf16 hi/lo)
__device__ __nv_bfloat16 g_Qh[(size_t)NBH * NTOK * DH];           // [bh][n][d] (x8 scaled)
__device__ __nv_bfloat16 g_Ql[(size_t)NBH * NTOK * DH];
__device__ __nv_bfloat16 g_Kh[(size_t)NBH * NTOK * DH];           // [bh][n][d]
__device__ __nv_bfloat16 g_Kl[(size_t)NBH * NTOK * DH];
__device__ __nv_bfloat16 g_Vh[(size_t)NBH * DH * NTOK];           // [bh][d][n]
__device__ __nv_bfloat16 g_Vl[(size_t)NBH * DH * NTOK];

// ---------------------------------------------------------------------------
// Helpers (portable PTX: ldmatrix + mma.sync, sm_80+)
// ---------------------------------------------------------------------------
__device__ __forceinline__ uint32_t smem_to_u32(const void* p) {
    uint32_t a;
    asm("{ .reg .u64 t; cvta.to.shared.u64 t, %1; cvt.u32.u64 %0, t; }" : "=r"(a) : "l"(p));
    return a;
}
__device__ __forceinline__ void ldsm_x4(uint32_t* r, uint32_t a) {
    asm volatile("ldmatrix.sync.aligned.m8n8.x4.shared.b16 {%0,%1,%2,%3}, [%4];"
        : "=r"(r[0]), "=r"(r[1]), "=r"(r[2]), "=r"(r[3]) : "r"(a));
}
__device__ __forceinline__ void mma_bf16(float* d, const uint32_t* a, const uint32_t* b) {
    asm volatile("mma.sync.aligned.m16n8k16.row.col.f32.bf16.bf16.f32 "
        "{%0,%1,%2,%3}, {%4,%5,%6,%7}, {%8,%9}, {%0,%1,%2,%3};"
        : "+f"(d[0]), "+f"(d[1]), "+f"(d[2]), "+f"(d[3])
        : "r"(a[0]), "r"(a[1]), "r"(a[2]), "r"(a[3]), "r"(b[0]), "r"(b[1]));
}
// pack two floats -> bf16x2 register (lo in low half)
__device__ __forceinline__ uint32_t pack_bf16(float lo, float hi) {
    uint32_t r;
    asm("cvt.rn.bf16x2.f32 %0, %1, %2;" : "=r"(r) : "f"(hi), "f"(lo));
    return r;
}

// ---------------------------------------------------------------------------
// Split + transpose: src[R][C] fp32 -> dh/dl[C][R] bf16 (hi/lo)
// ---------------------------------------------------------------------------
__device__ __forceinline__ void split_transpose_body(const float* __restrict__ src,
    __nv_bfloat16* __restrict__ dh, __nv_bfloat16* __restrict__ dl, int R, int C)
{
    __shared__ float tile[32][33];
    size_t bo = (size_t)blockIdx.z * R * C;
    int c0 = blockIdx.x << 5, r0 = blockIdx.y << 5;
    int tx = threadIdx.x & 31, ty = threadIdx.x >> 5;
#pragma unroll
    for (int i = 0; i < 32; i += 8)
        tile[ty + i][tx] = src[bo + (size_t)(r0 + ty + i) * C + c0 + tx];
    __syncthreads();
#pragma unroll
    for (int i = 0; i < 32; i += 8) {
        float v = tile[tx][ty + i];
        __nv_bfloat16 hv = __float2bfloat16(v);
        float lo = v - __bfloat162float(hv);
        size_t o = bo + (size_t)(c0 + ty + i) * R + (r0 + tx);
        dh[o] = hv;
        dl[o] = __float2bfloat16(lo);
    }
}
__global__ void split_x_kernel(const float* __restrict__ x)  { split_transpose_body(x, g_Xh, g_Xl, DIMC, NTOK); }
__global__ void split_wq_kernel(const float* __restrict__ w) { split_transpose_body(w, g_Wqh, g_Wql, DIMC, 3 * DIMC); }
__global__ void split_wp_kernel(const float* __restrict__ w) { split_transpose_body(w, g_Wph, g_Wpl, DIMC, DIMC); }

// ---------------------------------------------------------------------------
// Repack fp32 g_qkv -> bf16 hi/lo attention operands.
// Q,K: [bh][d][n] -> [bh][n][d] (transpose); V: [bh][d][n] stays. Q scaled x8.
// Grid: (32 n-tiles, 2 d-tiles, 3*96), 256 threads.
// ---------------------------------------------------------------------------
__global__ void repack_qkv() {
    int z = blockIdx.z, kq = z / NBH, bh = z % NBH;
    int n0 = blockIdx.x << 5, d0 = blockIdx.y << 5;
    int tx = threadIdx.x & 31, ty = threadIdx.x >> 5;
    const float* src = g_qkv + ((size_t)kq * NBH + bh) * DH * NTOK;
    __shared__ float tile[32][33];
    float sc = (kq == 0) ? 8.f : 1.f;
#pragma unroll
    for (int i = 0; i < 32; i += 8)
        tile[ty + i][tx] = src[(size_t)(d0 + ty + i) * NTOK + n0 + tx] * sc;
    __syncthreads();
    if (kq < 2) {
        __nv_bfloat16* dh = (kq == 0) ? g_Qh : g_Kh;
        __nv_bfloat16* dl = (kq == 0) ? g_Ql : g_Kl;
#pragma unroll
        for (int i = 0; i < 32; i += 8) {
            float v = tile[tx][ty + i];                       // d=d0+tx, n=n0+ty+i
            __nv_bfloat16 hv = __float2bfloat16(v);
            float lo = v - __bfloat162float(hv);
            size_t o = ((size_t)bh * NTOK + n0 + ty + i) * DH + d0 + tx;
            dh[o] = hv; dl[o] = __float2bfloat16(lo);
        }
    } else {
#pragma unroll
        for (int i = 0; i < 32; i += 8) {
            float v = tile[ty + i][tx];                       // d=d0+ty+i, n=n0+tx
            __nv_bfloat16 hv = __float2bfloat16(v);
            float lo = v - __bfloat162float(hv);
            size_t o = ((size_t)bh * DH + d0 + ty + i) * NTOK + n0 + tx;
            g_Vh[o] = hv; g_Vl[o] = __float2bfloat16(lo);
        }
    }
}

// ---------------------------------------------------------------------------
// bf16x3 mma.sync GEMM (unchanged from R3): C[128x128] = A[m][k] * B[n][k]^T
// ---------------------------------------------------------------------------
#define SA_STRIDE 72
#define TILE_BYTES (128 * SA_STRIDE * 2)

__device__ __forceinline__ void load_tile(const __nv_bfloat16* __restrict__ g,
    size_t row0, __nv_bfloat16* s, int kc, int t)
{
#pragma unroll
    for (int p = 0; p < 4; p++) {
        int lin = p * 256 + t;
        int row = lin >> 3, seg = lin & 7;
        uint4 v = *(const uint4*)(g + (row0 + row) * (size_t)DIMC + kc + seg * 8);
        *(uint4*)(s + row * SA_STRIDE + seg * 8) = v;
    }
}

__device__ __forceinline__ void gemm_mma(const __nv_bfloat16* __restrict__ Ah,
    const __nv_bfloat16* __restrict__ Al, const __nv_bfloat16* __restrict__ Bh,
    const __nv_bfloat16* __restrict__ Bl, float* __restrict__ outp, int mode)
{
    extern __shared__ char smem[];
    const uint32_t sb = smem_to_u32(smem);
    __nv_bfloat16* sAh = (__nv_bfloat16*)smem;
    __nv_bfloat16* sAl = sAh + 128 * SA_STRIDE;
    __nv_bfloat16* sBh = sAl + 128 * SA_STRIDE;
    __nv_bfloat16* sBl = sBh + 128 * SA_STRIDE;
    const uint32_t offAh = 0, offAl = TILE_BYTES, offBh = 2 * TILE_BYTES, offBl = 3 * TILE_BYTES;

    int t = threadIdx.x, lane = t & 31, wid = t >> 5;
    int wm = (wid & 1) * 64, wn = (wid >> 1) * 32;

    size_t m0 = (size_t)blockIdx.x * 128;
    int j0 = blockIdx.y * 128;

    float acc[4][4][4] = {};
    int arow = lane & 15;
    int acolp = (lane >> 4) << 3;
    int brow = (lane & 7) + ((lane >> 4) & 1) * 8;
    int bcolp = ((lane >> 3) & 1) * 8;

    for (int c = 0; c < 12; c++) {
        __syncthreads();
        int kc = c * 64;
        load_tile(Ah, m0, sAh, kc, t);
        load_tile(Al, m0, sAl, kc, t);
        load_tile(Bh, (size_t)j0, sBh, kc, t);
        load_tile(Bl, (size_t)j0, sBl, kc, t);
        __syncthreads();
#pragma unroll
        for (int ks = 0; ks < 4; ks++) {
            uint32_t ah[4][4], al[4][4], bh[2][4], bl[2][4];
            int acol = ks * 16 + acolp;
            int bcol = ks * 16 + bcolp;
#pragma unroll
            for (int mt = 0; mt < 4; mt++) {
                uint32_t ad = sb + offAh + ((wm + mt * 16 + arow) * SA_STRIDE + acol) * 2;
                ldsm_x4(ah[mt], ad);
                ldsm_x4(al[mt], ad + (offAl - offAh));
            }
#pragma unroll
            for (int ntp = 0; ntp < 2; ntp++) {
                uint32_t bd = sb + offBh + ((wn + ntp * 16 + brow) * SA_STRIDE + bcol) * 2;
                ldsm_x4(bh[ntp], bd);
                ldsm_x4(bl[ntp], bd + (offBl - offBh));
            }
#pragma unroll
            for (int mt = 0; mt < 4; mt++)
#pragma unroll
                for (int nt = 0; nt < 4; nt++) {
                    const uint32_t* bph = &bh[nt >> 1][(nt & 1) * 2];
                    const uint32_t* bpl = &bl[nt >> 1][(nt & 1) * 2];
                    mma_bf16(acc[mt][nt], ah[mt], bph);
                    mma_bf16(acc[mt][nt], al[mt], bph);
                    mma_bf16(acc[mt][nt], ah[mt], bpl);
                }
        }
    }

    __syncthreads();
    float* Cs = (float*)smem;
    int g = lane >> 2, tq = lane & 3;
#pragma unroll
    for (int mt = 0; mt < 4; mt++)
#pragma unroll
        for (int nt = 0; nt < 4; nt++) {
            int ml = wm + mt * 16 + g;
            int jl = wn + nt * 8 + tq * 2;
            Cs[jl * 132 + ml]           = acc[mt][nt][0];
            Cs[(jl + 1) * 132 + ml]     = acc[mt][nt][1];
            Cs[jl * 132 + ml + 8]       = acc[mt][nt][2];
            Cs[(jl + 1) * 132 + ml + 8] = acc[mt][nt][3];
        }
    __syncthreads();

    int bq = (int)(m0 >> 10);
    int n0 = (int)(m0 & 1023);
#pragma unroll
    for (int r = 0; r < 16; r++) {
        int e = r * 256 + t;
        int jl = e >> 5, seg = e & 31;
        float4 v = *(float4*)&Cs[jl * 132 + seg * 4];
        int j = j0 + jl;
        if (mode == 0) {
            int h = j % 12, kq = (j / 12) % 3, d = j / 36;
            *(float4*)&outp[((((size_t)kq * NB + bq) * HEADS + h) * DH + d) * NTOK + n0 + seg * 4] = v;
        } else {
            *(float4*)&outp[((size_t)bq * DIMC + j) * NTOK + n0 + seg * 4] = v;
        }
    }
}

__global__ void __launch_bounds__(256, 1) qkv_mma() {
    gemm_mma(g_Xh, g_Xl, g_Wqh, g_Wql, g_qkv, 0);
}
__global__ void __launch_bounds__(256, 1) proj_mma(float* __restrict__ out) {
    gemm_mma(g_Ch, g_Cl, g_Wph, g_Wpl, out, 1);
}

// ---------------------------------------------------------------------------
// Tensorized flash attention (bf16x3). Block = (128 q rows, one head).
// 8 warps, each owns 16 q rows x full 64-key tile x full 64 d.
// smem: Qh/Ql [128][72], Kh/Kl [64][72], Vh/Vl [64][72] (V as [d][keys]).
// ---------------------------------------------------------------------------
#define ATT_SMEM (128*72*2*2 + 64*72*2*4)   // 73728 B

__global__ void __launch_bounds__(256) attn_mma() {
    extern __shared__ char sm[];
    const uint32_t sb = smem_to_u32(sm);
    const uint32_t oQh = 0, oQl = 18432, oKh = 36864, oKl = 46080, oVh = 55296, oVl = 64512;
    __nv_bfloat16* sQh = (__nv_bfloat16*)(sm + oQh);
    __nv_bfloat16* sQl = (__nv_bfloat16*)(sm + oQl);
    __nv_bfloat16* sKh = (__nv_bfloat16*)(sm + oKh);
    __nv_bfloat16* sKl = (__nv_bfloat16*)(sm + oKl);
    __nv_bfloat16* sVh = (__nv_bfloat16*)(sm + oVh);
    __nv_bfloat16* sVl = (__nv_bfloat16*)(sm + oVl);

    int t = threadIdx.x, lane = t & 31, wid = t >> 5;
    int bh = blockIdx.y, qn0 = blockIdx.x << 7;

    const __nv_bfloat16* Qhg = g_Qh + ((size_t)bh * NTOK + qn0) * DH;
    const __nv_bfloat16* Qlg = g_Ql + ((size_t)bh * NTOK + qn0) * DH;
    const __nv_bfloat16* Khg = g_Kh + (size_t)bh * NTOK * DH;
    const __nv_bfloat16* Klg = g_Kl + (size_t)bh * NTOK * DH;
    const __nv_bfloat16* Vhg = g_Vh + (size_t)bh * DH * NTOK;
    const __nv_bfloat16* Vlg = g_Vl + (size_t)bh * DH * NTOK;

    // Load Q tile (128 rows x 64 d)
#pragma unroll
    for (int p = 0; p < 4; p++) {
        int idx = p * 256 + t;
        int row = idx >> 3, seg = idx & 7;
        *(uint4*)(sQh + row * 72 + seg * 8) = *(const uint4*)(Qhg + row * DH + seg * 8);
        *(uint4*)(sQl + row * 72 + seg * 8) = *(const uint4*)(Qlg + row * DH + seg * 8);
    }

    float o[8][4] = {};
    float m0 = -1e30f, m1 = -1e30f, l0 = 0.f, l1 = 0.f;

    int arow = lane & 15, acolp = (lane >> 4) << 3;
    int brow = (lane & 7) + ((lane >> 4) & 1) * 8;
    int bcolp = ((lane >> 3) & 1) * 8;

    for (int kt = 0; kt < 16; kt++) {
        __syncthreads();
        // K tile (64 keys x 64 d), V tile (64 d x 64 keys)
#pragma unroll
        for (int p = 0; p < 2; p++) {
            int idx = p * 256 + t;
            int row = idx >> 3, seg = idx & 7;
            *(uint4*)(sKh + row * 72 + seg * 8) = *(const uint4*)(Khg + (size_t)(kt * 64 + row) * DH + seg * 8);
            *(uint4*)(sKl + row * 72 + seg * 8) = *(const uint4*)(Klg + (size_t)(kt * 64 + row) * DH + seg * 8);
            *(uint4*)(sVh + row * 72 + seg * 8) = *(const uint4*)(Vhg + (size_t)row * NTOK + kt * 64 + seg * 8);
            *(uint4*)(sVl + row * 72 + seg * 8) = *(const uint4*)(Vlg + (size_t)row * NTOK + kt * 64 + seg * 8);
        }
        __syncthreads();

        // --- S = Q K^T (bf16x3), warp rows = wid*16 .. +15
        float s[8][4] = {};
#pragma unroll
        for (int ks = 0; ks < 4; ks++) {
            uint32_t ah[4], al[4];
            uint32_t aq = sb + oQh + ((wid * 16 + arow) * 72 + ks * 16 + acolp) * 2;
            ldsm_x4(ah, aq);
            ldsm_x4(al, aq + (oQl - oQh));
#pragma unroll
            for (int ntp = 0; ntp < 4; ntp++) {
                uint32_t bhf[4], blf[4];
                uint32_t ba = sb + oKh + ((ntp * 16 + brow) * 72 + ks * 16 + bcolp) * 2;
                ldsm_x4(bhf, ba);
                ldsm_x4(blf, ba + (oKl - oKh));
#pragma unroll
                for (int half = 0; half < 2; half++) {
                    int nt = ntp * 2 + half;
                    mma_bf16(s[nt], ah, &bhf[half * 2]);
                    mma_bf16(s[nt], al, &bhf[half * 2]);
                    mma_bf16(s[nt], ah, &blf[half * 2]);
                }
            }
        }

        // --- online softmax (rows r0 = lane>>2, r1 = r0+8 within warp tile)
        float rm0 = -1e30f, rm1 = -1e30f;
#pragma unroll
        for (int nt = 0; nt < 8; nt++) {
            rm0 = fmaxf(rm0, fmaxf(s[nt][0], s[nt][1]));
            rm1 = fmaxf(rm1, fmaxf(s[nt][2], s[nt][3]));
        }
        rm0 = fmaxf(rm0, __shfl_xor_sync(0xffffffffu, rm0, 1));
        rm0 = fmaxf(rm0, __shfl_xor_sync(0xffffffffu, rm0, 2));
        rm1 = fmaxf(rm1, __shfl_xor_sync(0xffffffffu, rm1, 1));
        rm1 = fmaxf(rm1, __shfl_xor_sync(0xffffffffu, rm1, 2));
        float mn0 = fmaxf(m0, rm0), mn1 = fmaxf(m1, rm1);
        float alpha0 = __expf(m0 - mn0), alpha1 = __expf(m1 - mn1);
        m0 = mn0; m1 = mn1;
        float rs0 = 0.f, rs1 = 0.f;
#pragma unroll
        for (int nt = 0; nt < 8; nt++) {
            s[nt][0] = __expf(s[nt][0] - mn0);
            s[nt][1] = __expf(s[nt][1] - mn0);
            s[nt][2] = __expf(s[nt][2] - mn1);
            s[nt][3] = __expf(s[nt][3] - mn1);
            rs0 += s[nt][0] + s[nt][1];
            rs1 += s[nt][2] + s[nt][3];
        }
        rs0 += __shfl_xor_sync(0xffffffffu, rs0, 1);
        rs0 += __shfl_xor_sync(0xffffffffu, rs0, 2);
        rs1 += __shfl_xor_sync(0xffffffffu, rs1, 1);
        rs1 += __shfl_xor_sync(0xffffffffu, rs1, 2);
        l0 = l0 * alpha0 + rs0;
        l1 = l1 * alpha1 + rs1;
#pragma unroll
        for (int nt = 0; nt < 8; nt++) {
            o[nt][0] *= alpha0; o[nt][1] *= alpha0;
            o[nt][2] *= alpha1; o[nt][3] *= alpha1;
        }

        // --- pack P as A-fragments (hi + residual lo)
        uint32_t pah[4][4], pal[4][4];
#pragma unroll
        for (int ks = 0; ks < 4; ks++) {
#pragma unroll
            for (int q = 0; q < 4; q++) {
                int nt = ks * 2 + (q >> 1);
                float p0 = s[nt][(q & 1) * 2], p1 = s[nt][(q & 1) * 2 + 1];
                __nv_bfloat16 h0 = __float2bfloat16(p0), h1 = __float2bfloat16(p1);
                float r0f = p0 - __bfloat162float(h0), r1f = p1 - __bfloat162float(h1);
                pah[ks][q] = ((uint32_t)*(uint16_t*)&h1 << 16) | *(uint16_t*)&h0;
                pal[ks][q] = pack_bf16(r0f, r1f);
            }
        }

        // --- O += P V  (bf16x3)
#pragma unroll
        for (int ks = 0; ks < 4; ks++) {
#pragma unroll
            for (int ntp = 0; ntp < 4; ntp++) {
                uint32_t vhf[4], vlf[4];
                uint32_t va = sb + oVh + ((ntp * 16 + brow) * 72 + ks * 16 + bcolp) * 2;
                ldsm_x4(vhf, va);
                ldsm_x4(vlf, va + (oVl - oVh));
#pragma unroll
                for (int half = 0; half < 2; half++) {
                    int nt = ntp * 2 + half;
                    mma_bf16(o[nt], pah[ks], &vhf[half * 2]);
                    mma_bf16(o[nt], pal[ks], &vhf[half * 2]);
                    mma_bf16(o[nt], pah[ks], &vlf[half * 2]);
                }
            }
        }
    }

    // --- epilogue: normalize, split hi/lo, write ctx[b][n][c]
    float inv0 = 1.f / l0, inv1 = 1.f / l1;
    int b = bh / HEADS, h = bh % HEADS;
    int r0 = qn0 + wid * 16 + (lane >> 2);
    int cb = h * DH + (lane & 3) * 2;
#pragma unroll
    for (int nt = 0; nt < 8; nt++) {
        float v0 = o[nt][0] * inv0, v1 = o[nt][1] * inv0;
        float v2 = o[nt][2] * inv1, v3 = o[nt][3] * inv1;
        __nv_bfloat16 h0 = __float2bfloat16(v0), h1 = __float2bfloat16(v1);
        __nv_bfloat16 h2 = __float2bfloat16(v2), h3 = __float2bfloat16(v3);
        uint32_t hp0 = ((uint32_t)*(uint16_t*)&h1 << 16) | *(uint16_t*)&h0;
        uint32_t hp1 = ((uint32_t)*(uint16_t*)&h3 << 16) | *(uint16_t*)&h2;
        uint32_t lp0 = pack_bf16(v0 - __bfloat162float(h0), v1 - __bfloat162float(h1));
        uint32_t lp1 = pack_bf16(v2 - __bfloat162float(h2), v3 - __bfloat162float(h3));
        size_t o0 = ((size_t)b * NTOK + r0) * DIMC + cb + nt * 8;
        size_t o1 = ((size_t)b * NTOK + r0 + 8) * DIMC + cb + nt * 8;
        *(uint32_t*)(g_Ch + o0) = hp0;
        *(uint32_t*)(g_Cl + o0) = lp0;
        *(uint32_t*)(g_Ch + o1) = hp1;
        *(uint32_t*)(g_Cl + o1) = lp1;
    }
}

// ---------------------------------------------------------------------------
extern "C" void kernel_launch(void* const* d_in, const int* in_sizes, int n_in,
                              void* d_out, int out_size) {
    const float* x      = (const float*)d_in[0];
    const float* w_qkv  = (const float*)d_in[1];
    const float* w_proj = (const float*)d_in[2];
    float* out = (float*)d_out;

    const int gemm_smem = 4 * TILE_BYTES;   // 73728 B
    cudaFuncSetAttribute(qkv_mma,  cudaFuncAttributeMaxDynamicSharedMemorySize, gemm_smem);
    cudaFuncSetAttribute(proj_mma, cudaFuncAttributeMaxDynamicSharedMemorySize, gemm_smem);
    cudaFuncSetAttribute(attn_mma, cudaFuncAttributeMaxDynamicSharedMemorySize, ATT_SMEM);

    split_x_kernel <<<dim3(NTOK / 32, DIMC / 32, NB), 256>>>(x);
    split_wq_kernel<<<dim3(3 * DIMC / 32, DIMC / 32, 1), 256>>>(w_qkv);
    split_wp_kernel<<<dim3(DIMC / 32, DIMC / 32, 1), 256>>>(w_proj);
    qkv_mma <<<dim3(64, 18), 256, gemm_smem>>>();
    repack_qkv<<<dim3(32, 2, 3 * NBH), 256>>>();
    attn_mma<<<dim3(NTOK / 128, NBH), 256, ATT_SMEM>>>();
    proj_mma<<<dim3(64, 6), 256, gemm_smem>>>(out);
}

// round 5
// speedup vs baseline: 4.4771x; 1.0563x over previous
#include <cuda_runtime.h>
#include <cuda_bf16.h>
#include <cstdint>
#include <math.h>

#define DIMC 768
#define HEADS 12
#define NB 8
#define NTOK 1024
#define DH 64
#define NBH (NB * HEADS)

// ---------------------------------------------------------------------------
// Global scratch
// ---------------------------------------------------------------------------
__device__ float g_qkv[3ull * NBH * DH * NTOK];                   // [k][bh][d][n] fp32
__device__ __nv_bfloat16 g_Xh[(size_t)NB * NTOK * DIMC];          // tokens [m][k]
__device__ __nv_bfloat16 g_Xl[(size_t)NB * NTOK * DIMC];
__device__ __nv_bfloat16 g_Wqh[(size_t)3 * DIMC * DIMC];          // w_qkv^T [j][k]
__device__ __nv_bfloat16 g_Wql[(size_t)3 * DIMC * DIMC];
__device__ __nv_bfloat16 g_Wph[(size_t)DIMC * DIMC];              // w_proj^T [j][k]
__device__ __nv_bfloat16 g_Wpl[(size_t)DIMC * DIMC];
__device__ __nv_bfloat16 g_Ch[(size_t)NB * NTOK * DIMC];          // ctx [m][k]
__device__ __nv_bfloat16 g_Cl[(size_t)NB * NTOK * DIMC];
// Attention operands (bf16 hi/lo)
__device__ __nv_bfloat16 g_Qh[(size_t)NBH * NTOK * DH];           // [bh][n][d] (x8 scaled)
__device__ __nv_bfloat16 g_Ql[(size_t)NBH * NTOK * DH];
__device__ __nv_bfloat16 g_Kh[(size_t)NBH * NTOK * DH];           // [bh][n][d]
__device__ __nv_bfloat16 g_Kl[(size_t)NBH * NTOK * DH];
__device__ __nv_bfloat16 g_Vh[(size_t)NBH * DH * NTOK];           // [bh][d][n]
__device__ __nv_bfloat16 g_Vl[(size_t)NBH * DH * NTOK];

// ---------------------------------------------------------------------------
// Helpers (portable PTX: ldmatrix + mma.sync + cp.async, sm_80+)
// ---------------------------------------------------------------------------
__device__ __forceinline__ uint32_t smem_to_u32(const void* p) {
    uint32_t a;
    asm("{ .reg .u64 t; cvta.to.shared.u64 t, %1; cvt.u32.u64 %0, t; }" : "=r"(a) : "l"(p));
    return a;
}
__device__ __forceinline__ void ldsm_x4(uint32_t* r, uint32_t a) {
    asm volatile("ldmatrix.sync.aligned.m8n8.x4.shared.b16 {%0,%1,%2,%3}, [%4];"
        : "=r"(r[0]), "=r"(r[1]), "=r"(r[2]), "=r"(r[3]) : "r"(a));
}
__device__ __forceinline__ void mma_bf16(float* d, const uint32_t* a, const uint32_t* b) {
    asm volatile("mma.sync.aligned.m16n8k16.row.col.f32.bf16.bf16.f32 "
        "{%0,%1,%2,%3}, {%4,%5,%6,%7}, {%8,%9}, {%0,%1,%2,%3};"
        : "+f"(d[0]), "+f"(d[1]), "+f"(d[2]), "+f"(d[3])
        : "r"(a[0]), "r"(a[1]), "r"(a[2]), "r"(a[3]), "r"(b[0]), "r"(b[1]));
}
__device__ __forceinline__ uint32_t pack_bf16(float lo, float hi) {
    uint32_t r;
    asm("cvt.rn.bf16x2.f32 %0, %1, %2;" : "=r"(r) : "f"(hi), "f"(lo));
    return r;
}
__device__ __forceinline__ void cp_async16(uint32_t sa, const void* g) {
    asm volatile("cp.async.cg.shared.global [%0], [%1], 16;" :: "r"(sa), "l"(g));
}
#define CP_COMMIT() asm volatile("cp.async.commit_group;" ::: "memory")
#define CP_WAIT(N)  asm volatile("cp.async.wait_group %0;" :: "n"(N) : "memory")

// ---------------------------------------------------------------------------
// Split + transpose: src[R][C] fp32 -> dh/dl[C][R] bf16 (hi/lo)
// ---------------------------------------------------------------------------
__device__ __forceinline__ void split_transpose_body(const float* __restrict__ src,
    __nv_bfloat16* __restrict__ dh, __nv_bfloat16* __restrict__ dl, int R, int C)
{
    __shared__ float tile[32][33];
    size_t bo = (size_t)blockIdx.z * R * C;
    int c0 = blockIdx.x << 5, r0 = blockIdx.y << 5;
    int tx = threadIdx.x & 31, ty = threadIdx.x >> 5;
#pragma unroll
    for (int i = 0; i < 32; i += 8)
        tile[ty + i][tx] = src[bo + (size_t)(r0 + ty + i) * C + c0 + tx];
    __syncthreads();
#pragma unroll
    for (int i = 0; i < 32; i += 8) {
        float v = tile[tx][ty + i];
        __nv_bfloat16 hv = __float2bfloat16(v);
        float lo = v - __bfloat162float(hv);
        size_t o = bo + (size_t)(c0 + ty + i) * R + (r0 + tx);
        dh[o] = hv;
        dl[o] = __float2bfloat16(lo);
    }
}
__global__ void split_x_kernel(const float* __restrict__ x)  { split_transpose_body(x, g_Xh, g_Xl, DIMC, NTOK); }
__global__ void split_wq_kernel(const float* __restrict__ w) { split_transpose_body(w, g_Wqh, g_Wql, DIMC, 3 * DIMC); }
__global__ void split_wp_kernel(const float* __restrict__ w) { split_transpose_body(w, g_Wph, g_Wpl, DIMC, DIMC); }

// ---------------------------------------------------------------------------
// Repack fp32 g_qkv -> bf16 hi/lo attention operands.
// ---------------------------------------------------------------------------
__global__ void repack_qkv() {
    int z = blockIdx.z, kq = z / NBH, bh = z % NBH;
    int n0 = blockIdx.x << 5, d0 = blockIdx.y << 5;
    int tx = threadIdx.x & 31, ty = threadIdx.x >> 5;
    const float* src = g_qkv + ((size_t)kq * NBH + bh) * DH * NTOK;
    __shared__ float tile[32][33];
    float sc = (kq == 0) ? 8.f : 1.f;
#pragma unroll
    for (int i = 0; i < 32; i += 8)
        tile[ty + i][tx] = src[(size_t)(d0 + ty + i) * NTOK + n0 + tx] * sc;
    __syncthreads();
    if (kq < 2) {
        __nv_bfloat16* dh = (kq == 0) ? g_Qh : g_Kh;
        __nv_bfloat16* dl = (kq == 0) ? g_Ql : g_Kl;
#pragma unroll
        for (int i = 0; i < 32; i += 8) {
            float v = tile[tx][ty + i];
            __nv_bfloat16 hv = __float2bfloat16(v);
            float lo = v - __bfloat162float(hv);
            size_t o = ((size_t)bh * NTOK + n0 + ty + i) * DH + d0 + tx;
            dh[o] = hv; dl[o] = __float2bfloat16(lo);
        }
    } else {
#pragma unroll
        for (int i = 0; i < 32; i += 8) {
            float v = tile[ty + i][tx];
            __nv_bfloat16 hv = __float2bfloat16(v);
            float lo = v - __bfloat162float(hv);
            size_t o = ((size_t)bh * DH + d0 + ty + i) * NTOK + n0 + tx;
            g_Vh[o] = hv; g_Vl[o] = __float2bfloat16(lo);
        }
    }
}

// ---------------------------------------------------------------------------
// bf16x3 mma.sync GEMM with cp.async double buffering.
// C[128x128] = A[m][k] * B[n][k]^T, K=768, 12 chunks of 64.
// ---------------------------------------------------------------------------
#define SA_STRIDE 72
#define TILE_BYTES (128 * SA_STRIDE * 2)         // 18432
#define STAGE_BYTES (4 * TILE_BYTES)             // 73728
#define GEMM_SMEM (2 * STAGE_BYTES)              // 147456

__device__ __forceinline__ void load_tile_async(const __nv_bfloat16* __restrict__ g,
    size_t row0, uint32_t sdst, int kc, int t)
{
#pragma unroll
    for (int p = 0; p < 4; p++) {
        int lin = p * 256 + t;
        int row = lin >> 3, seg = lin & 7;
        cp_async16(sdst + (uint32_t)(row * SA_STRIDE + seg * 8) * 2,
                   g + (row0 + row) * (size_t)DIMC + kc + seg * 8);
    }
}

__device__ __forceinline__ void gemm_mma(const __nv_bfloat16* __restrict__ Ah,
    const __nv_bfloat16* __restrict__ Al, const __nv_bfloat16* __restrict__ Bh,
    const __nv_bfloat16* __restrict__ Bl, float* __restrict__ outp, int mode)
{
    extern __shared__ char smem[];
    const uint32_t sb = smem_to_u32(smem);

    int t = threadIdx.x, lane = t & 31, wid = t >> 5;
    int wm = (wid & 1) * 64, wn = (wid >> 1) * 32;

    size_t m0 = (size_t)blockIdx.x * 128;
    int j0 = blockIdx.y * 128;

    float acc[4][4][4] = {};
    int arow = lane & 15;
    int acolp = (lane >> 4) << 3;
    int brow = (lane & 7) + ((lane >> 4) & 1) * 8;
    int bcolp = ((lane >> 3) & 1) * 8;

    // prefetch chunk 0
    {
        uint32_t st = sb;
        load_tile_async(Ah, m0, st, 0, t);
        load_tile_async(Al, m0, st + TILE_BYTES, 0, t);
        load_tile_async(Bh, (size_t)j0, st + 2 * TILE_BYTES, 0, t);
        load_tile_async(Bl, (size_t)j0, st + 3 * TILE_BYTES, 0, t);
        CP_COMMIT();
    }

    for (int c = 0; c < 12; c++) {
        if (c + 1 < 12) {
            uint32_t st = sb + ((c + 1) & 1) * STAGE_BYTES;
            int kc = (c + 1) * 64;
            load_tile_async(Ah, m0, st, kc, t);
            load_tile_async(Al, m0, st + TILE_BYTES, kc, t);
            load_tile_async(Bh, (size_t)j0, st + 2 * TILE_BYTES, kc, t);
            load_tile_async(Bl, (size_t)j0, st + 3 * TILE_BYTES, kc, t);
            CP_COMMIT();
            CP_WAIT(1);
        } else {
            CP_WAIT(0);
        }
        __syncthreads();

        uint32_t base = sb + (c & 1) * STAGE_BYTES;
#pragma unroll
        for (int ks = 0; ks < 4; ks++) {
            uint32_t ah[4][4], al[4][4], bh[2][4], bl[2][4];
            int acol = ks * 16 + acolp;
            int bcol = ks * 16 + bcolp;
#pragma unroll
            for (int mt = 0; mt < 4; mt++) {
                uint32_t ad = base + ((wm + mt * 16 + arow) * SA_STRIDE + acol) * 2;
                ldsm_x4(ah[mt], ad);
                ldsm_x4(al[mt], ad + TILE_BYTES);
            }
#pragma unroll
            for (int ntp = 0; ntp < 2; ntp++) {
                uint32_t bd = base + 2 * TILE_BYTES + ((wn + ntp * 16 + brow) * SA_STRIDE + bcol) * 2;
                ldsm_x4(bh[ntp], bd);
                ldsm_x4(bl[ntp], bd + TILE_BYTES);
            }
#pragma unroll
            for (int mt = 0; mt < 4; mt++)
#pragma unroll
                for (int nt = 0; nt < 4; nt++) {
                    const uint32_t* bph = &bh[nt >> 1][(nt & 1) * 2];
                    const uint32_t* bpl = &bl[nt >> 1][(nt & 1) * 2];
                    mma_bf16(acc[mt][nt], ah[mt], bph);
                    mma_bf16(acc[mt][nt], al[mt], bph);
                    mma_bf16(acc[mt][nt], ah[mt], bpl);
                }
        }
        __syncthreads();
    }

    // Stage C through smem for coalesced stores. Cs[128 j][132 m] fp32.
    float* Cs = (float*)smem;
    int g = lane >> 2, tq = lane & 3;
#pragma unroll
    for (int mt = 0; mt < 4; mt++)
#pragma unroll
        for (int nt = 0; nt < 4; nt++) {
            int ml = wm + mt * 16 + g;
            int jl = wn + nt * 8 + tq * 2;
            Cs[jl * 132 + ml]           = acc[mt][nt][0];
            Cs[(jl + 1) * 132 + ml]     = acc[mt][nt][1];
            Cs[jl * 132 + ml + 8]       = acc[mt][nt][2];
            Cs[(jl + 1) * 132 + ml + 8] = acc[mt][nt][3];
        }
    __syncthreads();

    int bq = (int)(m0 >> 10);
    int n0 = (int)(m0 & 1023);
#pragma unroll
    for (int r = 0; r < 16; r++) {
        int e = r * 256 + t;
        int jl = e >> 5, seg = e & 31;
        float4 v = *(float4*)&Cs[jl * 132 + seg * 4];
        int j = j0 + jl;
        if (mode == 0) {
            int h = j % 12, kq = (j / 12) % 3, d = j / 36;
            *(float4*)&outp[((((size_t)kq * NB + bq) * HEADS + h) * DH + d) * NTOK + n0 + seg * 4] = v;
        } else {
            *(float4*)&outp[((size_t)bq * DIMC + j) * NTOK + n0 + seg * 4] = v;
        }
    }
}

__global__ void __launch_bounds__(256, 1) qkv_mma() {
    gemm_mma(g_Xh, g_Xl, g_Wqh, g_Wql, g_qkv, 0);
}
__global__ void __launch_bounds__(256, 1) proj_mma(float* __restrict__ out) {
    gemm_mma(g_Ch, g_Cl, g_Wph, g_Wpl, out, 1);
}

// ---------------------------------------------------------------------------
// Tensorized flash attention (bf16x3) with cp.async double-buffered K/V.
// smem: Q hi/lo [128][72] at 0; 2 stages of (Kh,Kl,Vh,Vl)[64][72].
// ---------------------------------------------------------------------------
#define KV_TILE 9216                              // 64*72*2
#define KV_STAGE (4 * KV_TILE)                    // 36864
#define ATT_Q (2 * 18432)                         // 36864
#define ATT_SMEM (ATT_Q + 2 * KV_STAGE)           // 110592

__global__ void __launch_bounds__(256) attn_mma() {
    extern __shared__ char sm[];
    const uint32_t sb = smem_to_u32(sm);
    const uint32_t oQh = 0, oQl = 18432;
    __nv_bfloat16* sQh = (__nv_bfloat16*)(sm + oQh);
    __nv_bfloat16* sQl = (__nv_bfloat16*)(sm + oQl);

    int t = threadIdx.x, lane = t & 31, wid = t >> 5;
    int bh = blockIdx.y, qn0 = blockIdx.x << 7;

    const __nv_bfloat16* Qhg = g_Qh + ((size_t)bh * NTOK + qn0) * DH;
    const __nv_bfloat16* Qlg = g_Ql + ((size_t)bh * NTOK + qn0) * DH;
    const __nv_bfloat16* Khg = g_Kh + (size_t)bh * NTOK * DH;
    const __nv_bfloat16* Klg = g_Kl + (size_t)bh * NTOK * DH;
    const __nv_bfloat16* Vhg = g_Vh + (size_t)bh * DH * NTOK;
    const __nv_bfloat16* Vlg = g_Vl + (size_t)bh * DH * NTOK;

    // prefetch KV tile 0
    {
        uint32_t st = sb + ATT_Q;
#pragma unroll
        for (int p = 0; p < 2; p++) {
            int idx = p * 256 + t;
            int row = idx >> 3, seg = idx & 7;
            uint32_t so = (uint32_t)(row * 72 + seg * 8) * 2;
            cp_async16(st + so,               Khg + (size_t)row * DH + seg * 8);
            cp_async16(st + KV_TILE + so,     Klg + (size_t)row * DH + seg * 8);
            cp_async16(st + 2 * KV_TILE + so, Vhg + (size_t)row * NTOK + seg * 8);
            cp_async16(st + 3 * KV_TILE + so, Vlg + (size_t)row * NTOK + seg * 8);
        }
        CP_COMMIT();
    }

    // Load Q tile (128 rows x 64 d)
#pragma unroll
    for (int p = 0; p < 4; p++) {
        int idx = p * 256 + t;
        int row = idx >> 3, seg = idx & 7;
        *(uint4*)(sQh + row * 72 + seg * 8) = *(const uint4*)(Qhg + row * DH + seg * 8);
        *(uint4*)(sQl + row * 72 + seg * 8) = *(const uint4*)(Qlg + row * DH + seg * 8);
    }

    float o[8][4] = {};
    float m0 = -1e30f, m1 = -1e30f, l0 = 0.f, l1 = 0.f;

    int arow = lane & 15, acolp = (lane >> 4) << 3;
    int brow = (lane & 7) + ((lane >> 4) & 1) * 8;
    int bcolp = ((lane >> 3) & 1) * 8;

    for (int kt = 0; kt < 16; kt++) {
        if (kt + 1 < 16) {
            uint32_t st = sb + ATT_Q + ((kt + 1) & 1) * KV_STAGE;
            int jb = (kt + 1) * 64;
#pragma unroll
            for (int p = 0; p < 2; p++) {
                int idx = p * 256 + t;
                int row = idx >> 3, seg = idx & 7;
                uint32_t so = (uint32_t)(row * 72 + seg * 8) * 2;
                cp_async16(st + so,               Khg + (size_t)(jb + row) * DH + seg * 8);
                cp_async16(st + KV_TILE + so,     Klg + (size_t)(jb + row) * DH + seg * 8);
                cp_async16(st + 2 * KV_TILE + so, Vhg + (size_t)row * NTOK + jb + seg * 8);
                cp_async16(st + 3 * KV_TILE + so, Vlg + (size_t)row * NTOK + jb + seg * 8);
            }
            CP_COMMIT();
            CP_WAIT(1);
        } else {
            CP_WAIT(0);
        }
        __syncthreads();

        uint32_t kv = sb + ATT_Q + (kt & 1) * KV_STAGE;

        // --- S = Q K^T (bf16x3)
        float s[8][4] = {};
#pragma unroll
        for (int ks = 0; ks < 4; ks++) {
            uint32_t ah[4], al[4];
            uint32_t aq = sb + oQh + ((wid * 16 + arow) * 72 + ks * 16 + acolp) * 2;
            ldsm_x4(ah, aq);
            ldsm_x4(al, aq + (oQl - oQh));
#pragma unroll
            for (int ntp = 0; ntp < 4; ntp++) {
                uint32_t bhf[4], blf[4];
                uint32_t ba = kv + ((ntp * 16 + brow) * 72 + ks * 16 + bcolp) * 2;
                ldsm_x4(bhf, ba);
                ldsm_x4(blf, ba + KV_TILE);
#pragma unroll
                for (int half = 0; half < 2; half++) {
                    int nt = ntp * 2 + half;
                    mma_bf16(s[nt], ah, &bhf[half * 2]);
                    mma_bf16(s[nt], al, &bhf[half * 2]);
                    mma_bf16(s[nt], ah, &blf[half * 2]);
                }
            }
        }

        // --- online softmax
        float rm0 = -1e30f, rm1 = -1e30f;
#pragma unroll
        for (int nt = 0; nt < 8; nt++) {
            rm0 = fmaxf(rm0, fmaxf(s[nt][0], s[nt][1]));
            rm1 = fmaxf(rm1, fmaxf(s[nt][2], s[nt][3]));
        }
        rm0 = fmaxf(rm0, __shfl_xor_sync(0xffffffffu, rm0, 1));
        rm0 = fmaxf(rm0, __shfl_xor_sync(0xffffffffu, rm0, 2));
        rm1 = fmaxf(rm1, __shfl_xor_sync(0xffffffffu, rm1, 1));
        rm1 = fmaxf(rm1, __shfl_xor_sync(0xffffffffu, rm1, 2));
        float mn0 = fmaxf(m0, rm0), mn1 = fmaxf(m1, rm1);
        float alpha0 = __expf(m0 - mn0), alpha1 = __expf(m1 - mn1);
        m0 = mn0; m1 = mn1;
        float rs0 = 0.f, rs1 = 0.f;
#pragma unroll
        for (int nt = 0; nt < 8; nt++) {
            s[nt][0] = __expf(s[nt][0] - mn0);
            s[nt][1] = __expf(s[nt][1] - mn0);
            s[nt][2] = __expf(s[nt][2] - mn1);
            s[nt][3] = __expf(s[nt][3] - mn1);
            rs0 += s[nt][0] + s[nt][1];
            rs1 += s[nt][2] + s[nt][3];
        }
        rs0 += __shfl_xor_sync(0xffffffffu, rs0, 1);
        rs0 += __shfl_xor_sync(0xffffffffu, rs0, 2);
        rs1 += __shfl_xor_sync(0xffffffffu, rs1, 1);
        rs1 += __shfl_xor_sync(0xffffffffu, rs1, 2);
        l0 = l0 * alpha0 + rs0;
        l1 = l1 * alpha1 + rs1;
#pragma unroll
        for (int nt = 0; nt < 8; nt++) {
            o[nt][0] *= alpha0; o[nt][1] *= alpha0;
            o[nt][2] *= alpha1; o[nt][3] *= alpha1;
        }

        // --- pack P as A-fragments (hi + residual lo)
        uint32_t pah[4][4], pal[4][4];
#pragma unroll
        for (int ks = 0; ks < 4; ks++) {
#pragma unroll
            for (int q = 0; q < 4; q++) {
                int nt = ks * 2 + (q >> 1);
                float p0 = s[nt][(q & 1) * 2], p1 = s[nt][(q & 1) * 2 + 1];
                __nv_bfloat16 h0 = __float2bfloat16(p0), h1 = __float2bfloat16(p1);
                float r0f = p0 - __bfloat162float(h0), r1f = p1 - __bfloat162float(h1);
                pah[ks][q] = ((uint32_t)*(uint16_t*)&h1 << 16) | *(uint16_t*)&h0;
                pal[ks][q] = pack_bf16(r0f, r1f);
            }
        }

        // --- O += P V (bf16x3)
#pragma unroll
        for (int ks = 0; ks < 4; ks++) {
#pragma unroll
            for (int ntp = 0; ntp < 4; ntp++) {
                uint32_t vhf[4], vlf[4];
                uint32_t va = kv + 2 * KV_TILE + ((ntp * 16 + brow) * 72 + ks * 16 + bcolp) * 2;
                ldsm_x4(vhf, va);
                ldsm_x4(vlf, va + KV_TILE);
#pragma unroll
                for (int half = 0; half < 2; half++) {
                    int nt = ntp * 2 + half;
                    mma_bf16(o[nt], pah[ks], &vhf[half * 2]);
                    mma_bf16(o[nt], pal[ks], &vhf[half * 2]);
                    mma_bf16(o[nt], pah[ks], &vlf[half * 2]);
                }
            }
        }
        __syncthreads();
    }

    // --- epilogue: normalize, split hi/lo, write ctx[b][n][c]
    float inv0 = 1.f / l0, inv1 = 1.f / l1;
    int b = bh / HEADS, h = bh % HEADS;
    int r0 = qn0 + wid * 16 + (lane >> 2);
    int cb = h * DH + (lane & 3) * 2;
#pragma unroll
    for (int nt = 0; nt < 8; nt++) {
        float v0 = o[nt][0] * inv0, v1 = o[nt][1] * inv0;
        float v2 = o[nt][2] * inv1, v3 = o[nt][3] * inv1;
        __nv_bfloat16 h0 = __float2bfloat16(v0), h1 = __float2bfloat16(v1);
        __nv_bfloat16 h2 = __float2bfloat16(v2), h3 = __float2bfloat16(v3);
        uint32_t hp0 = ((uint32_t)*(uint16_t*)&h1 << 16) | *(uint16_t*)&h0;
        uint32_t hp1 = ((uint32_t)*(uint16_t*)&h3 << 16) | *(uint16_t*)&h2;
        uint32_t lp0 = pack_bf16(v0 - __bfloat162float(h0), v1 - __bfloat162float(h1));
        uint32_t lp1 = pack_bf16(v2 - __bfloat162float(h2), v3 - __bfloat162float(h3));
        size_t o0 = ((size_t)b * NTOK + r0) * DIMC + cb + nt * 8;
        size_t o1 = ((size_t)b * NTOK + r0 + 8) * DIMC + cb + nt * 8;
        *(uint32_t*)(g_Ch + o0) = hp0;
        *(uint32_t*)(g_Cl + o0) = lp0;
        *(uint32_t*)(g_Ch + o1) = hp1;
        *(uint32_t*)(g_Cl + o1) = lp1;
    }
}

// ---------------------------------------------------------------------------
extern "C" void kernel_launch(void* const* d_in, const int* in_sizes, int n_in,
                              void* d_out, int out_size) {
    const float* x      = (const float*)d_in[0];
    const float* w_qkv  = (const float*)d_in[1];
    const float* w_proj = (const float*)d_in[2];
    float* out = (float*)d_out;

    cudaFuncSetAttribute(qkv_mma,  cudaFuncAttributeMaxDynamicSharedMemorySize, GEMM_SMEM);
    cudaFuncSetAttribute(proj_mma, cudaFuncAttributeMaxDynamicSharedMemorySize, GEMM_SMEM);
    cudaFuncSetAttribute(attn_mma, cudaFuncAttributeMaxDynamicSharedMemorySize, ATT_SMEM);

    split_x_kernel <<<dim3(NTOK / 32, DIMC / 32, NB), 256>>>(x);
    split_wq_kernel<<<dim3(3 * DIMC / 32, DIMC / 32, 1), 256>>>(w_qkv);
    split_wp_kernel<<<dim3(DIMC / 32, DIMC / 32, 1), 256>>>(w_proj);
    qkv_mma <<<dim3(64, 18), 256, GEMM_SMEM>>>();
    repack_qkv<<<dim3(32, 2, 3 * NBH), 256>>>();
    attn_mma<<<dim3(NTOK / 128, NBH), 256, ATT_SMEM>>>();
    proj_mma<<<dim3(64, 6), 256, GEMM_SMEM>>>(out);
}

// round 6
// speedup vs baseline: 4.6458x; 1.0377x over previous
#include <cuda_runtime.h>
#include <cuda_bf16.h>
#include <cstdint>
#include <math.h>

#define DIMC 768
#define HEADS 12
#define NB 8
#define NTOK 1024
#define DH 64
#define NBH (NB * HEADS)

// ---------------------------------------------------------------------------
// Global scratch (no fp32 qkv anymore — GEMM writes attention operands direct)
// ---------------------------------------------------------------------------
__device__ __nv_bfloat16 g_Xh[(size_t)NB * NTOK * DIMC];          // tokens [m][k]
__device__ __nv_bfloat16 g_Xl[(size_t)NB * NTOK * DIMC];
__device__ __nv_bfloat16 g_Wqh[(size_t)3 * DIMC * DIMC];          // w_qkv^T permuted [j'][k]
__device__ __nv_bfloat16 g_Wql[(size_t)3 * DIMC * DIMC];
__device__ __nv_bfloat16 g_Wph[(size_t)DIMC * DIMC];              // w_proj^T [j][k]
__device__ __nv_bfloat16 g_Wpl[(size_t)DIMC * DIMC];
__device__ __nv_bfloat16 g_Ch[(size_t)NB * NTOK * DIMC];          // ctx [m][k]
__device__ __nv_bfloat16 g_Cl[(size_t)NB * NTOK * DIMC];
// Attention operands (bf16 hi/lo)
__device__ __nv_bfloat16 g_Qh[(size_t)NBH * NTOK * DH];           // [bh][n][d] (x8 via W)
__device__ __nv_bfloat16 g_Ql[(size_t)NBH * NTOK * DH];
__device__ __nv_bfloat16 g_Kh[(size_t)NBH * NTOK * DH];           // [bh][n][d]
__device__ __nv_bfloat16 g_Kl[(size_t)NBH * NTOK * DH];
__device__ __nv_bfloat16 g_Vh[(size_t)NBH * DH * NTOK];           // [bh][d][n]
__device__ __nv_bfloat16 g_Vl[(size_t)NBH * DH * NTOK];

// ---------------------------------------------------------------------------
// Helpers (portable PTX: ldmatrix + mma.sync + cp.async, sm_80+)
// ---------------------------------------------------------------------------
__device__ __forceinline__ uint32_t smem_to_u32(const void* p) {
    uint32_t a;
    asm("{ .reg .u64 t; cvta.to.shared.u64 t, %1; cvt.u32.u64 %0, t; }" : "=r"(a) : "l"(p));
    return a;
}
__device__ __forceinline__ void ldsm_x4(uint32_t* r, uint32_t a) {
    asm volatile("ldmatrix.sync.aligned.m8n8.x4.shared.b16 {%0,%1,%2,%3}, [%4];"
        : "=r"(r[0]), "=r"(r[1]), "=r"(r[2]), "=r"(r[3]) : "r"(a));
}
// NON-volatile: pure register op, lets ptxas software-pipeline the HMMA chain.
__device__ __forceinline__ void mma_bf16(float* d, const uint32_t* a, const uint32_t* b) {
    asm("mma.sync.aligned.m16n8k16.row.col.f32.bf16.bf16.f32 "
        "{%0,%1,%2,%3}, {%4,%5,%6,%7}, {%8,%9}, {%0,%1,%2,%3};"
        : "+f"(d[0]), "+f"(d[1]), "+f"(d[2]), "+f"(d[3])
        : "r"(a[0]), "r"(a[1]), "r"(a[2]), "r"(a[3]), "r"(b[0]), "r"(b[1]));
}
__device__ __forceinline__ uint32_t pack_bf16(float lo, float hi) {
    uint32_t r;
    asm("cvt.rn.bf16x2.f32 %0, %1, %2;" : "=r"(r) : "f"(hi), "f"(lo));
    return r;
}
__device__ __forceinline__ uint32_t pack2(__nv_bfloat16 a, __nv_bfloat16 b) {
    return ((uint32_t)*(uint16_t*)&b << 16) | *(uint16_t*)&a;
}
__device__ __forceinline__ void cp_async16(uint32_t sa, const void* g) {
    asm volatile("cp.async.cg.shared.global [%0], [%1], 16;" :: "r"(sa), "l"(g));
}
#define CP_COMMIT() asm volatile("cp.async.commit_group;" ::: "memory")
#define CP_WAIT(N)  asm volatile("cp.async.wait_group %0;" :: "n"(N) : "memory")

// ---------------------------------------------------------------------------
// Split + transpose: src[R][C] fp32 -> dh/dl[C][R] bf16 (hi/lo)
// ---------------------------------------------------------------------------
__device__ __forceinline__ void split_transpose_body(const float* __restrict__ src,
    __nv_bfloat16* __restrict__ dh, __nv_bfloat16* __restrict__ dl, int R, int C)
{
    __shared__ float tile[32][33];
    size_t bo = (size_t)blockIdx.z * R * C;
    int c0 = blockIdx.x << 5, r0 = blockIdx.y << 5;
    int tx = threadIdx.x & 31, ty = threadIdx.x >> 5;
#pragma unroll
    for (int i = 0; i < 32; i += 8)
        tile[ty + i][tx] = src[bo + (size_t)(r0 + ty + i) * C + c0 + tx];
    __syncthreads();
#pragma unroll
    for (int i = 0; i < 32; i += 8) {
        float v = tile[tx][ty + i];
        __nv_bfloat16 hv = __float2bfloat16(v);
        float lo = v - __bfloat162float(hv);
        size_t o = bo + (size_t)(c0 + ty + i) * R + (r0 + tx);
        dh[o] = hv;
        dl[o] = __float2bfloat16(lo);
    }
}
__global__ void split_x_kernel(const float* __restrict__ x)  { split_transpose_body(x, g_Xh, g_Xl, DIMC, NTOK); }
__global__ void split_wp_kernel(const float* __restrict__ w) { split_transpose_body(w, g_Wph, g_Wpl, DIMC, DIMC); }

// w_qkv split with column permutation j -> j' = (j%36)*64 + j/36  (d innermost),
// and x8 scale folded into Q columns (j%36 < 12).
__global__ void split_wq_kernel(const float* __restrict__ w) {
    __shared__ float tile[32][33];
    int c0 = blockIdx.x << 5, r0 = blockIdx.y << 5;   // c over j (2304), r over k (768)
    int tx = threadIdx.x & 31, ty = threadIdx.x >> 5;
#pragma unroll
    for (int i = 0; i < 32; i += 8)
        tile[ty + i][tx] = w[(size_t)(r0 + ty + i) * (3 * DIMC) + c0 + tx];
    __syncthreads();
#pragma unroll
    for (int i = 0; i < 32; i += 8) {
        int j = c0 + ty + i;
        float v = tile[tx][ty + i];
        int rem = j % 36, d = j / 36;
        if (rem < 12) v *= 8.f;                        // Q scale
        int jp = rem * 64 + d;
        __nv_bfloat16 hv = __float2bfloat16(v);
        float lo = v - __bfloat162float(hv);
        size_t o = (size_t)jp * DIMC + r0 + tx;
        g_Wqh[o] = hv;
        g_Wql[o] = __float2bfloat16(lo);
    }
}

// ---------------------------------------------------------------------------
// bf16x3 mma.sync GEMM with cp.async double buffering, term-major MMA order.
// C[128x128] = A[m][k] * B[n][k]^T, K=768, 12 chunks of 64.
// mode 0: qkv (write Q/K [bh][n][d], V [bh][d][n] bf16 hi/lo)
// mode 1: proj (write fp32 out [b][c][n])
// ---------------------------------------------------------------------------
#define SA_STRIDE 72
#define TILE_BYTES (128 * SA_STRIDE * 2)         // 18432
#define STAGE_BYTES (4 * TILE_BYTES)             // 73728
#define GEMM_SMEM (2 * STAGE_BYTES)              // 147456

__device__ __forceinline__ void load_tile_async(const __nv_bfloat16* __restrict__ g,
    size_t row0, uint32_t sdst, int kc, int t)
{
#pragma unroll
    for (int p = 0; p < 4; p++) {
        int lin = p * 256 + t;
        int row = lin >> 3, seg = lin & 7;
        cp_async16(sdst + (uint32_t)(row * SA_STRIDE + seg * 8) * 2,
                   g + (row0 + row) * (size_t)DIMC + kc + seg * 8);
    }
}

__device__ __forceinline__ void gemm_mma(const __nv_bfloat16* __restrict__ Ah,
    const __nv_bfloat16* __restrict__ Al, const __nv_bfloat16* __restrict__ Bh,
    const __nv_bfloat16* __restrict__ Bl, float* __restrict__ outp, int mode)
{
    extern __shared__ char smem[];
    const uint32_t sb = smem_to_u32(smem);

    int t = threadIdx.x, lane = t & 31, wid = t >> 5;
    int wm = (wid & 1) * 64, wn = (wid >> 1) * 32;

    size_t m0 = (size_t)blockIdx.x * 128;
    int j0 = blockIdx.y * 128;

    float acc[4][4][4] = {};
    int arow = lane & 15;
    int acolp = (lane >> 4) << 3;
    int brow = (lane & 7) + ((lane >> 4) & 1) * 8;
    int bcolp = ((lane >> 3) & 1) * 8;

    // prefetch chunk 0
    {
        uint32_t st = sb;
        load_tile_async(Ah, m0, st, 0, t);
        load_tile_async(Al, m0, st + TILE_BYTES, 0, t);
        load_tile_async(Bh, (size_t)j0, st + 2 * TILE_BYTES, 0, t);
        load_tile_async(Bl, (size_t)j0, st + 3 * TILE_BYTES, 0, t);
        CP_COMMIT();
    }

    for (int c = 0; c < 12; c++) {
        if (c + 1 < 12) {
            uint32_t st = sb + ((c + 1) & 1) * STAGE_BYTES;
            int kc = (c + 1) * 64;
            load_tile_async(Ah, m0, st, kc, t);
            load_tile_async(Al, m0, st + TILE_BYTES, kc, t);
            load_tile_async(Bh, (size_t)j0, st + 2 * TILE_BYTES, kc, t);
            load_tile_async(Bl, (size_t)j0, st + 3 * TILE_BYTES, kc, t);
            CP_COMMIT();
            CP_WAIT(1);
        } else {
            CP_WAIT(0);
        }
        __syncthreads();

        uint32_t base = sb + (c & 1) * STAGE_BYTES;
#pragma unroll
        for (int ks = 0; ks < 4; ks++) {
            uint32_t ah[4][4], al[4][4], bh[2][4], bl[2][4];
            int acol = ks * 16 + acolp;
            int bcol = ks * 16 + bcolp;
#pragma unroll
            for (int mt = 0; mt < 4; mt++) {
                uint32_t ad = base + ((wm + mt * 16 + arow) * SA_STRIDE + acol) * 2;
                ldsm_x4(ah[mt], ad);
                ldsm_x4(al[mt], ad + TILE_BYTES);
            }
#pragma unroll
            for (int ntp = 0; ntp < 2; ntp++) {
                uint32_t bd = base + 2 * TILE_BYTES + ((wn + ntp * 16 + brow) * SA_STRIDE + bcol) * 2;
                ldsm_x4(bh[ntp], bd);
                ldsm_x4(bl[ntp], bd + TILE_BYTES);
            }
            // term-major: 16 independent accumulators between reuses
#pragma unroll
            for (int mt = 0; mt < 4; mt++)
#pragma unroll
                for (int nt = 0; nt < 4; nt++)
                    mma_bf16(acc[mt][nt], ah[mt], &bh[nt >> 1][(nt & 1) * 2]);
#pragma unroll
            for (int mt = 0; mt < 4; mt++)
#pragma unroll
                for (int nt = 0; nt < 4; nt++)
                    mma_bf16(acc[mt][nt], al[mt], &bh[nt >> 1][(nt & 1) * 2]);
#pragma unroll
            for (int mt = 0; mt < 4; mt++)
#pragma unroll
                for (int nt = 0; nt < 4; nt++)
                    mma_bf16(acc[mt][nt], ah[mt], &bl[nt >> 1][(nt & 1) * 2]);
        }
        __syncthreads();
    }

    float* Cs = (float*)smem;
    int g = lane >> 2, tq = lane & 3;
    int bq = (int)(m0 >> 10);
    int n0 = (int)(m0 & 1023);

    if (mode == 1) {
        // [j][m] staging, fp32 out[b][c][n]
#pragma unroll
        for (int mt = 0; mt < 4; mt++)
#pragma unroll
            for (int nt = 0; nt < 4; nt++) {
                int ml = wm + mt * 16 + g;
                int jl = wn + nt * 8 + tq * 2;
                Cs[jl * 132 + ml]           = acc[mt][nt][0];
                Cs[(jl + 1) * 132 + ml]     = acc[mt][nt][1];
                Cs[jl * 132 + ml + 8]       = acc[mt][nt][2];
                Cs[(jl + 1) * 132 + ml + 8] = acc[mt][nt][3];
            }
        __syncthreads();
#pragma unroll
        for (int r = 0; r < 16; r++) {
            int e = r * 256 + t;
            int jl = e >> 5, seg = e & 31;
            float4 v = *(float4*)&Cs[jl * 132 + seg * 4];
            *(float4*)&outp[((size_t)bq * DIMC + j0 + jl) * NTOK + n0 + seg * 4] = v;
        }
        return;
    }

    // mode 0: qkv. Tile covers kqh groups (2*by, 2*by+1); kq = by/6.
    int by = blockIdx.y;
    int kq = by / 6;
    if (kq < 2) {
        // stage [m][j] (j = d within group), write Q/K [bh][n][d]
#pragma unroll
        for (int mt = 0; mt < 4; mt++)
#pragma unroll
            for (int nt = 0; nt < 4; nt++) {
                int r = wm + mt * 16 + g;
                int cc = wn + nt * 8 + tq * 2;
                *(float2*)&Cs[r * 132 + cc]       = make_float2(acc[mt][nt][0], acc[mt][nt][1]);
                *(float2*)&Cs[(r + 8) * 132 + cc] = make_float2(acc[mt][nt][2], acc[mt][nt][3]);
            }
        __syncthreads();
        __nv_bfloat16* Dh = (kq == 0) ? g_Qh : g_Kh;
        __nv_bfloat16* Dl = (kq == 0) ? g_Ql : g_Kl;
#pragma unroll
        for (int it = 0; it < 8; it++) {
            int idx = it * 256 + t;
            int kqh_l = idx >> 10;
            int m = (idx >> 3) & 127;
            int dseg = idx & 7;
            int h = (by * 2 + kqh_l) % 12;
            int bh_i = bq * 12 + h;
            float f[8];
            *(float4*)&f[0] = *(float4*)&Cs[m * 132 + kqh_l * 64 + dseg * 8];
            *(float4*)&f[4] = *(float4*)&Cs[m * 132 + kqh_l * 64 + dseg * 8 + 4];
            uint32_t hp[4], lp[4];
#pragma unroll
            for (int q = 0; q < 4; q++) {
                __nv_bfloat16 h0 = __float2bfloat16(f[2 * q]);
                __nv_bfloat16 h1 = __float2bfloat16(f[2 * q + 1]);
                hp[q] = pack2(h0, h1);
                lp[q] = pack_bf16(f[2 * q] - __bfloat162float(h0),
                                  f[2 * q + 1] - __bfloat162float(h1));
            }
            size_t o = ((size_t)bh_i * NTOK + n0 + m) * DH + dseg * 8;
            *(uint4*)(Dh + o) = *(uint4*)hp;
            *(uint4*)(Dl + o) = *(uint4*)lp;
        }
    } else {
        // stage [j][m], write V [bh][d][n]
#pragma unroll
        for (int mt = 0; mt < 4; mt++)
#pragma unroll
            for (int nt = 0; nt < 4; nt++) {
                int ml = wm + mt * 16 + g;
                int jl = wn + nt * 8 + tq * 2;
                Cs[jl * 132 + ml]           = acc[mt][nt][0];
                Cs[(jl + 1) * 132 + ml]     = acc[mt][nt][1];
                Cs[jl * 132 + ml + 8]       = acc[mt][nt][2];
                Cs[(jl + 1) * 132 + ml + 8] = acc[mt][nt][3];
            }
        __syncthreads();
#pragma unroll
        for (int it = 0; it < 8; it++) {
            int idx = it * 256 + t;
            int jl = idx >> 4;
            int seg = idx & 15;
            int kqh_l = jl >> 6, d = jl & 63;
            int h = (by * 2 + kqh_l) % 12;
            int bh_i = bq * 12 + h;
            float f[8];
            *(float4*)&f[0] = *(float4*)&Cs[jl * 132 + seg * 8];
            *(float4*)&f[4] = *(float4*)&Cs[jl * 132 + seg * 8 + 4];
            uint32_t hp[4], lp[4];
#pragma unroll
            for (int q = 0; q < 4; q++) {
                __nv_bfloat16 h0 = __float2bfloat16(f[2 * q]);
                __nv_bfloat16 h1 = __float2bfloat16(f[2 * q + 1]);
                hp[q] = pack2(h0, h1);
                lp[q] = pack_bf16(f[2 * q] - __bfloat162float(h0),
                                  f[2 * q + 1] - __bfloat162float(h1));
            }
            size_t o = ((size_t)bh_i * DH + d) * NTOK + n0 + seg * 8;
            *(uint4*)(g_Vh + o) = *(uint4*)hp;
            *(uint4*)(g_Vl + o) = *(uint4*)lp;
        }
    }
}

__global__ void __launch_bounds__(256, 1) qkv_mma() {
    gemm_mma(g_Xh, g_Xl, g_Wqh, g_Wql, (float*)0, 0);
}
__global__ void __launch_bounds__(256, 1) proj_mma(float* __restrict__ out) {
    gemm_mma(g_Ch, g_Cl, g_Wph, g_Wpl, out, 1);
}

// ---------------------------------------------------------------------------
// Tensorized flash attention (bf16x3) with cp.async double-buffered K/V,
// term-major MMA ordering.
// ---------------------------------------------------------------------------
#define KV_TILE 9216                              // 64*72*2
#define KV_STAGE (4 * KV_TILE)                    // 36864
#define ATT_Q (2 * 18432)                         // 36864
#define ATT_SMEM (ATT_Q + 2 * KV_STAGE)           // 110592

__global__ void __launch_bounds__(256) attn_mma() {
    extern __shared__ char sm[];
    const uint32_t sb = smem_to_u32(sm);
    const uint32_t oQh = 0, oQl = 18432;
    __nv_bfloat16* sQh = (__nv_bfloat16*)(sm + oQh);
    __nv_bfloat16* sQl = (__nv_bfloat16*)(sm + oQl);

    int t = threadIdx.x, lane = t & 31, wid = t >> 5;
    int bh = blockIdx.y, qn0 = blockIdx.x << 7;

    const __nv_bfloat16* Qhg = g_Qh + ((size_t)bh * NTOK + qn0) * DH;
    const __nv_bfloat16* Qlg = g_Ql + ((size_t)bh * NTOK + qn0) * DH;
    const __nv_bfloat16* Khg = g_Kh + (size_t)bh * NTOK * DH;
    const __nv_bfloat16* Klg = g_Kl + (size_t)bh * NTOK * DH;
    const __nv_bfloat16* Vhg = g_Vh + (size_t)bh * DH * NTOK;
    const __nv_bfloat16* Vlg = g_Vl + (size_t)bh * DH * NTOK;

    // prefetch KV tile 0
    {
        uint32_t st = sb + ATT_Q;
#pragma unroll
        for (int p = 0; p < 2; p++) {
            int idx = p * 256 + t;
            int row = idx >> 3, seg = idx & 7;
            uint32_t so = (uint32_t)(row * 72 + seg * 8) * 2;
            cp_async16(st + so,               Khg + (size_t)row * DH + seg * 8);
            cp_async16(st + KV_TILE + so,     Klg + (size_t)row * DH + seg * 8);
            cp_async16(st + 2 * KV_TILE + so, Vhg + (size_t)row * NTOK + seg * 8);
            cp_async16(st + 3 * KV_TILE + so, Vlg + (size_t)row * NTOK + seg * 8);
        }
        CP_COMMIT();
    }

    // Load Q tile (128 rows x 64 d)
#pragma unroll
    for (int p = 0; p < 4; p++) {
        int idx = p * 256 + t;
        int row = idx >> 3, seg = idx & 7;
        *(uint4*)(sQh + row * 72 + seg * 8) = *(const uint4*)(Qhg + row * DH + seg * 8);
        *(uint4*)(sQl + row * 72 + seg * 8) = *(const uint4*)(Qlg + row * DH + seg * 8);
    }

    float o[8][4] = {};
    float m0 = -1e30f, m1 = -1e30f, l0 = 0.f, l1 = 0.f;

    int arow = lane & 15, acolp = (lane >> 4) << 3;
    int brow = (lane & 7) + ((lane >> 4) & 1) * 8;
    int bcolp = ((lane >> 3) & 1) * 8;

    for (int kt = 0; kt < 16; kt++) {
        if (kt + 1 < 16) {
            uint32_t st = sb + ATT_Q + ((kt + 1) & 1) * KV_STAGE;
            int jb = (kt + 1) * 64;
#pragma unroll
            for (int p = 0; p < 2; p++) {
                int idx = p * 256 + t;
                int row = idx >> 3, seg = idx & 7;
                uint32_t so = (uint32_t)(row * 72 + seg * 8) * 2;
                cp_async16(st + so,               Khg + (size_t)(jb + row) * DH + seg * 8);
                cp_async16(st + KV_TILE + so,     Klg + (size_t)(jb + row) * DH + seg * 8);
                cp_async16(st + 2 * KV_TILE + so, Vhg + (size_t)row * NTOK + jb + seg * 8);
                cp_async16(st + 3 * KV_TILE + so, Vlg + (size_t)row * NTOK + jb + seg * 8);
            }
            CP_COMMIT();
            CP_WAIT(1);
        } else {
            CP_WAIT(0);
        }
        __syncthreads();

        uint32_t kv = sb + ATT_Q + (kt & 1) * KV_STAGE;

        // --- S = Q K^T (bf16x3, term-major)
        float s[8][4] = {};
#pragma unroll
        for (int ks = 0; ks < 4; ks++) {
            uint32_t ah[4], al[4], bhf[4][4], blf[4][4];
            uint32_t aq = sb + oQh + ((wid * 16 + arow) * 72 + ks * 16 + acolp) * 2;
            ldsm_x4(ah, aq);
            ldsm_x4(al, aq + (oQl - oQh));
#pragma unroll
            for (int ntp = 0; ntp < 4; ntp++) {
                uint32_t ba = kv + ((ntp * 16 + brow) * 72 + ks * 16 + bcolp) * 2;
                ldsm_x4(bhf[ntp], ba);
                ldsm_x4(blf[ntp], ba + KV_TILE);
            }
#pragma unroll
            for (int nt = 0; nt < 8; nt++)
                mma_bf16(s[nt], ah, &bhf[nt >> 1][(nt & 1) * 2]);
#pragma unroll
            for (int nt = 0; nt < 8; nt++)
                mma_bf16(s[nt], al, &bhf[nt >> 1][(nt & 1) * 2]);
#pragma unroll
            for (int nt = 0; nt < 8; nt++)
                mma_bf16(s[nt], ah, &blf[nt >> 1][(nt & 1) * 2]);
        }

        // --- online softmax
        float rm0 = -1e30f, rm1 = -1e30f;
#pragma unroll
        for (int nt = 0; nt < 8; nt++) {
            rm0 = fmaxf(rm0, fmaxf(s[nt][0], s[nt][1]));
            rm1 = fmaxf(rm1, fmaxf(s[nt][2], s[nt][3]));
        }
        rm0 = fmaxf(rm0, __shfl_xor_sync(0xffffffffu, rm0, 1));
        rm0 = fmaxf(rm0, __shfl_xor_sync(0xffffffffu, rm0, 2));
        rm1 = fmaxf(rm1, __shfl_xor_sync(0xffffffffu, rm1, 1));
        rm1 = fmaxf(rm1, __shfl_xor_sync(0xffffffffu, rm1, 2));
        float mn0 = fmaxf(m0, rm0), mn1 = fmaxf(m1, rm1);
        float alpha0 = __expf(m0 - mn0), alpha1 = __expf(m1 - mn1);
        m0 = mn0; m1 = mn1;
        float rs0 = 0.f, rs1 = 0.f;
#pragma unroll
        for (int nt = 0; nt < 8; nt++) {
            s[nt][0] = __expf(s[nt][0] - mn0);
            s[nt][1] = __expf(s[nt][1] - mn0);
            s[nt][2] = __expf(s[nt][2] - mn1);
            s[nt][3] = __expf(s[nt][3] - mn1);
            rs0 += s[nt][0] + s[nt][1];
            rs1 += s[nt][2] + s[nt][3];
        }
        rs0 += __shfl_xor_sync(0xffffffffu, rs0, 1);
        rs0 += __shfl_xor_sync(0xffffffffu, rs0, 2);
        rs1 += __shfl_xor_sync(0xffffffffu, rs1, 1);
        rs1 += __shfl_xor_sync(0xffffffffu, rs1, 2);
        l0 = l0 * alpha0 + rs0;
        l1 = l1 * alpha1 + rs1;
#pragma unroll
        for (int nt = 0; nt < 8; nt++) {
            o[nt][0] *= alpha0; o[nt][1] *= alpha0;
            o[nt][2] *= alpha1; o[nt][3] *= alpha1;
        }

        // --- pack P as A-fragments (hi + residual lo)
        uint32_t pah[4][4], pal[4][4];
#pragma unroll
        for (int ks = 0; ks < 4; ks++) {
#pragma unroll
            for (int q = 0; q < 4; q++) {
                int nt = ks * 2 + (q >> 1);
                float p0 = s[nt][(q & 1) * 2], p1 = s[nt][(q & 1) * 2 + 1];
                __nv_bfloat16 h0 = __float2bfloat16(p0), h1 = __float2bfloat16(p1);
                float r0f = p0 - __bfloat162float(h0), r1f = p1 - __bfloat162float(h1);
                pah[ks][q] = pack2(h0, h1);
                pal[ks][q] = pack_bf16(r0f, r1f);
            }
        }

        // --- O += P V (bf16x3, term-major)
#pragma unroll
        for (int ks = 0; ks < 4; ks++) {
            uint32_t vhf[4][4], vlf[4][4];
#pragma unroll
            for (int ntp = 0; ntp < 4; ntp++) {
                uint32_t va = kv + 2 * KV_TILE + ((ntp * 16 + brow) * 72 + ks * 16 + bcolp) * 2;
                ldsm_x4(vhf[ntp], va);
                ldsm_x4(vlf[ntp], va + KV_TILE);
            }
#pragma unroll
            for (int nt = 0; nt < 8; nt++)
                mma_bf16(o[nt], pah[ks], &vhf[nt >> 1][(nt & 1) * 2]);
#pragma unroll
            for (int nt = 0; nt < 8; nt++)
                mma_bf16(o[nt], pal[ks], &vhf[nt >> 1][(nt & 1) * 2]);
#pragma unroll
            for (int nt = 0; nt < 8; nt++)
                mma_bf16(o[nt], pah[ks], &vlf[nt >> 1][(nt & 1) * 2]);
        }
        __syncthreads();
    }

    // --- epilogue: normalize, split hi/lo, write ctx[b][n][c]
    float inv0 = 1.f / l0, inv1 = 1.f / l1;
    int b = bh / HEADS, h = bh % HEADS;
    int r0 = qn0 + wid * 16 + (lane >> 2);
    int cb = h * DH + (lane & 3) * 2;
#pragma unroll
    for (int nt = 0; nt < 8; nt++) {
        float v0 = o[nt][0] * inv0, v1 = o[nt][1] * inv0;
        float v2 = o[nt][2] * inv1, v3 = o[nt][3] * inv1;
        __nv_bfloat16 h0 = __float2bfloat16(v0), h1 = __float2bfloat16(v1);
        __nv_bfloat16 h2 = __float2bfloat16(v2), h3 = __float2bfloat16(v3);
        uint32_t hp0 = pack2(h0, h1);
        uint32_t hp1 = pack2(h2, h3);
        uint32_t lp0 = pack_bf16(v0 - __bfloat162float(h0), v1 - __bfloat162float(h1));
        uint32_t lp1 = pack_bf16(v2 - __bfloat162float(h2), v3 - __bfloat162float(h3));
        size_t o0 = ((size_t)b * NTOK + r0) * DIMC + cb + nt * 8;
        size_t o1 = ((size_t)b * NTOK + r0 + 8) * DIMC + cb + nt * 8;
        *(uint32_t*)(g_Ch + o0) = hp0;
        *(uint32_t*)(g_Cl + o0) = lp0;
        *(uint32_t*)(g_Ch + o1) = hp1;
        *(uint32_t*)(g_Cl + o1) = lp1;
    }
}

// ---------------------------------------------------------------------------
extern "C" void kernel_launch(void* const* d_in, const int* in_sizes, int n_in,
                              void* d_out, int out_size) {
    const float* x      = (const float*)d_in[0];
    const float* w_qkv  = (const float*)d_in[1];
    const float* w_proj = (const float*)d_in[2];
    float* out = (float*)d_out;

    cudaFuncSetAttribute(qkv_mma,  cudaFuncAttributeMaxDynamicSharedMemorySize, GEMM_SMEM);
    cudaFuncSetAttribute(proj_mma, cudaFuncAttributeMaxDynamicSharedMemorySize, GEMM_SMEM);
    cudaFuncSetAttribute(attn_mma, cudaFuncAttributeMaxDynamicSharedMemorySize, ATT_SMEM);

    split_x_kernel <<<dim3(NTOK / 32, DIMC / 32, NB), 256>>>(x);
    split_wq_kernel<<<dim3(3 * DIMC / 32, DIMC / 32, 1), 256>>>(w_qkv);
    split_wp_kernel<<<dim3(DIMC / 32, DIMC / 32, 1), 256>>>(w_proj);
    qkv_mma <<<dim3(64, 18), 256, GEMM_SMEM>>>();
    attn_mma<<<dim3(NTOK / 128, NBH), 256, ATT_SMEM>>>();
    proj_mma<<<dim3(64, 6), 256, GEMM_SMEM>>>(out);
}